// round 9
// baseline (speedup 1.0000x reference)
#include <cuda_runtime.h>
#include <cuda_bf16.h>
#include <cstdint>

// Problem constants (fixed shapes)
#define BB 16384
#define DD 2048
#define HH 1024
#define EE 16
#define TOPC 409
#define KTOT 2080          // padded K: 2048 + 16 (spec) + 16 pad, %32==0

// ---------------------------------------------------------------------------
// Device global scratch (no runtime allocation allowed)
// ---------------------------------------------------------------------------
__device__ float g_h1[(size_t)BB * HH];
__device__ float g_h2[(size_t)BB * HH];
__device__ float g_spec[(size_t)BB * EE];
__device__ float g_sims[(size_t)BB * EE];
__device__ __nv_bfloat16 g_xth[(size_t)KTOT * BB];   // x^T hi, k-major [K][B]
__device__ __nv_bfloat16 g_xtl[(size_t)KTOT * BB];   // x^T lo
__device__ __nv_bfloat16 g_w1h[(size_t)KTOT * HH];
__device__ __nv_bfloat16 g_w1l[(size_t)KTOT * HH];
__device__ __nv_bfloat16 g_w2h[(size_t)KTOT * HH];
__device__ __nv_bfloat16 g_w2l[(size_t)KTOT * HH];
__device__ int g_cnt[3];

// ---------------------------------------------------------------------------
// helpers
// ---------------------------------------------------------------------------
__device__ __forceinline__ uint32_t smem_u32(const void* p) {
    uint32_t a;
    asm("{ .reg .u64 t; cvta.to.shared.u64 t, %1; cvt.u32.u64 %0, t; }" : "=r"(a) : "l"(p));
    return a;
}

#define CPA16(dst, src) \
    asm volatile("cp.async.cg.shared.global [%0], [%1], 16;" :: "r"(dst), "l"(src))
#define CPA_COMMIT() asm volatile("cp.async.commit_group;" ::: "memory")

#define LDSM4T(r0, r1, r2, r3, addr) \
    asm volatile("ldmatrix.sync.aligned.m8n8.x4.trans.shared.b16 {%0,%1,%2,%3}, [%4];" \
                 : "=r"(r0), "=r"(r1), "=r"(r2), "=r"(r3) : "r"(addr) : "memory")

#define MMA16816(d, a, b0, b1) \
    asm volatile("mma.sync.aligned.m16n8k16.row.col.f32.bf16.bf16.f32 " \
                 "{%0,%1,%2,%3}, {%4,%5,%6,%7}, {%8,%9}, {%0,%1,%2,%3};" \
                 : "+f"((d)[0]), "+f"((d)[1]), "+f"((d)[2]), "+f"((d)[3]) \
                 : "r"((a)[0]), "r"((a)[1]), "r"((a)[2]), "r"((a)[3]), \
                   "r"(b0), "r"(b1))

// ---------------------------------------------------------------------------
// split + transpose x: [B, D] fp32 -> xT hi/lo bf16 [KTOT][B]; zero k>=2048.
// ---------------------------------------------------------------------------
__global__ void split_xT_kernel(const float* __restrict__ x,
                                __nv_bfloat16* __restrict__ xh,
                                __nv_bfloat16* __restrict__ xl)
{
    __shared__ float t[64][33];
    int k0 = blockIdx.x * 32;        // 65 tiles
    int m0 = blockIdx.y * 64;        // 256 tiles
    int tid = threadIdx.x;

    int k = tid >> 3;                // 0..31
    int mm = (tid & 7) * 8;          // 0..56

    if (k0 < DD) {
        int r = tid >> 2;            // 0..63
        int c = (tid & 3) * 8;       // 0,8,16,24
        const float* src = x + (size_t)(m0 + r) * DD + k0 + c;
        float4 v0 = *(const float4*)src;
        float4 v1 = *(const float4*)(src + 4);
        t[r][c + 0] = v0.x; t[r][c + 1] = v0.y; t[r][c + 2] = v0.z; t[r][c + 3] = v0.w;
        t[r][c + 4] = v1.x; t[r][c + 5] = v1.y; t[r][c + 6] = v1.z; t[r][c + 7] = v1.w;
        __syncthreads();

        __nv_bfloat16 h8[8], l8[8];
#pragma unroll
        for (int j = 0; j < 8; ++j) {
            float v = t[mm + j][k];
            __nv_bfloat16 h = __float2bfloat16(v);
            h8[j] = h;
            l8[j] = __float2bfloat16(v - __bfloat162float(h));
        }
        *(uint4*)(xh + (size_t)(k0 + k) * BB + m0 + mm) = *(uint4*)h8;
        *(uint4*)(xl + (size_t)(k0 + k) * BB + m0 + mm) = *(uint4*)l8;
    } else {
        uint4 z = {0, 0, 0, 0};
        *(uint4*)(xh + (size_t)(k0 + k) * BB + m0 + mm) = z;
        *(uint4*)(xl + (size_t)(k0 + k) * BB + m0 + mm) = z;
    }
}

// ---------------------------------------------------------------------------
// split W: [Klim, 1024] fp32 -> hi/lo bf16 [KTOT][1024], zero past Klim
// ---------------------------------------------------------------------------
__global__ void split_w_kernel(const float* __restrict__ W, int Klim,
                               __nv_bfloat16* __restrict__ wh,
                               __nv_bfloat16* __restrict__ wl)
{
    int idx = blockIdx.x * 256 + threadIdx.x;   // over KTOT*1024
    int k = idx >> 10, n = idx & 1023;
    float v = (k < Klim) ? W[(size_t)k * HH + n] : 0.0f;
    __nv_bfloat16 h = __float2bfloat16(v);
    wh[idx] = h;
    wl[idx] = __float2bfloat16(v - __bfloat162float(h));
}

// ---------------------------------------------------------------------------
// HMMA split-bf16 GEMM: BK=32, 3-stage cp.async pipeline.
// CTA tile 128x128, 8 warps (2m x 4n), each warp 64x32.
// ---------------------------------------------------------------------------
#define STG_BYTES 32768
#define GEMM_SMEM (3 * STG_BYTES + 1024)

__device__ __forceinline__ void gemm_ld_stage(
    uint32_t db, int s, int c,
    const __nv_bfloat16* __restrict__ Ah, const __nv_bfloat16* __restrict__ Al,
    const __nv_bfloat16* __restrict__ Wh, const __nv_bfloat16* __restrict__ Wl,
    int m0, int n0, int tid)
{
    int k  = tid >> 3;                 // 0..31
    int mc = (tid & 7) * 2;            // chunk pair
    uint32_t base = db + s * STG_BYTES;
    uint32_t d0 = k * 256 + ((mc ^ (k & 7)) << 4);
    uint32_t d1 = k * 256 + (((mc + 1) ^ (k & 7)) << 4);
    size_t ka = (size_t)(c * 32 + k);
    const char* pah = (const char*)(Ah + ka * BB + m0 + mc * 8);
    const char* pal = (const char*)(Al + ka * BB + m0 + mc * 8);
    const char* pwh = (const char*)(Wh + ka * HH + n0 + mc * 8);
    const char* pwl = (const char*)(Wl + ka * HH + n0 + mc * 8);
    CPA16(base + d0,         pah);      CPA16(base + d1,         pah + 16);
    CPA16(base + 8192  + d0, pal);      CPA16(base + 8192  + d1, pal + 16);
    CPA16(base + 16384 + d0, pwh);      CPA16(base + 16384 + d1, pwh + 16);
    CPA16(base + 24576 + d0, pwl);      CPA16(base + 24576 + d1, pwl + 16);
    CPA_COMMIT();
}

__global__ __launch_bounds__(256, 1)
void gemm_mma(const __nv_bfloat16* __restrict__ Ah, const __nv_bfloat16* __restrict__ Al,
              const __nv_bfloat16* __restrict__ Wh, const __nv_bfloat16* __restrict__ Wl,
              const float* __restrict__ bias, float* __restrict__ C, int nch)
{
    extern __shared__ char smem[];
    uint32_t db = (smem_u32(smem) + 1023) & ~1023u;
    int tid = threadIdx.x, lane = tid & 31, wid = tid >> 5;
    int wm = wid >> 2, wn = wid & 3;
    int m0 = blockIdx.y * 128, n0 = blockIdx.x * 128;

    int q = lane >> 3, r = lane & 7;
    int kq = ((q >> 1) << 3) + r;       // 0..15
    int sw = kq & 7;
    uint32_t offA[4], offB[2];
#pragma unroll
    for (int mt = 0; mt < 4; ++mt) {
        int cc = wm * 8 + mt * 2 + (q & 1);
        offA[mt] = kq * 256 + ((cc ^ sw) << 4);
    }
#pragma unroll
    for (int bt = 0; bt < 2; ++bt) {
        int cc = wn * 4 + bt * 2 + (q & 1);
        offB[bt] = kq * 256 + ((cc ^ sw) << 4);
    }

    float acc[4][4][4] = {};

    // prologue: fill 3 stages
    gemm_ld_stage(db, 0, 0, Ah, Al, Wh, Wl, m0, n0, tid);
    gemm_ld_stage(db, 1, 1, Ah, Al, Wh, Wl, m0, n0, tid);
    gemm_ld_stage(db, 2, 2, Ah, Al, Wh, Wl, m0, n0, tid);

    int smod = 0;   // c % 3 tracked incrementally
    for (int c = 0; c < nch; ++c) {
        int rem = nch - 1 - c;
        if (rem >= 2)      asm volatile("cp.async.wait_group 2;" ::: "memory");
        else if (rem == 1) asm volatile("cp.async.wait_group 1;" ::: "memory");
        else               asm volatile("cp.async.wait_group 0;" ::: "memory");
        __syncthreads();

        uint32_t sbase = db + smod * STG_BYTES;
#pragma unroll
        for (int ks = 0; ks < 2; ++ks) {
            uint32_t sb = sbase + ks * 4096;
            uint32_t ah[4][4], al_[4][4], bh_[2][4], bl_[2][4];
#pragma unroll
            for (int mt = 0; mt < 4; ++mt) {
                LDSM4T(ah[mt][0],  ah[mt][1],  ah[mt][2],  ah[mt][3],  sb + offA[mt]);
                LDSM4T(al_[mt][0], al_[mt][1], al_[mt][2], al_[mt][3], sb + 8192 + offA[mt]);
            }
#pragma unroll
            for (int bt = 0; bt < 2; ++bt) {
                LDSM4T(bh_[bt][0], bh_[bt][1], bh_[bt][2], bh_[bt][3], sb + 16384 + offB[bt]);
                LDSM4T(bl_[bt][0], bl_[bt][1], bl_[bt][2], bl_[bt][3], sb + 24576 + offB[bt]);
            }
#pragma unroll
            for (int mt = 0; mt < 4; ++mt)
#pragma unroll
                for (int nt = 0; nt < 4; ++nt) {
                    int bt = nt >> 1, p = nt & 1;
                    MMA16816(acc[mt][nt], ah[mt], bh_[bt][p], bh_[bt][p + 2]);
                }
#pragma unroll
            for (int mt = 0; mt < 4; ++mt)
#pragma unroll
                for (int nt = 0; nt < 4; ++nt) {
                    int bt = nt >> 1, p = nt & 1;
                    MMA16816(acc[mt][nt], ah[mt], bl_[bt][p], bl_[bt][p + 2]);
                }
#pragma unroll
            for (int mt = 0; mt < 4; ++mt)
#pragma unroll
                for (int nt = 0; nt < 4; ++nt) {
                    int bt = nt >> 1, p = nt & 1;
                    MMA16816(acc[mt][nt], al_[mt], bh_[bt][p], bh_[bt][p + 2]);
                }
        }
        __syncthreads();
        if (c + 3 < nch)
            gemm_ld_stage(db, smod, c + 3, Ah, Al, Wh, Wl, m0, n0, tid);
        smod = (smod == 2) ? 0 : smod + 1;
    }

    int g = lane >> 2, t2 = (lane & 3) * 2;
#pragma unroll
    for (int nt = 0; nt < 4; ++nt) {
        int col = n0 + wn * 32 + nt * 8 + t2;
        float2 bv = *(const float2*)(bias + col);
#pragma unroll
        for (int mt = 0; mt < 4; ++mt) {
            int row = m0 + wm * 64 + mt * 16 + g;
            float2 o0, o1;
            o0.x = fmaxf(acc[mt][nt][0] + bv.x, 0.f);
            o0.y = fmaxf(acc[mt][nt][1] + bv.y, 0.f);
            o1.x = fmaxf(acc[mt][nt][2] + bv.x, 0.f);
            o1.y = fmaxf(acc[mt][nt][3] + bv.y, 0.f);
            *(float2*)(C + (size_t)row * HH + col) = o0;
            *(float2*)(C + (size_t)(row + 8) * HH + col) = o1;
        }
    }
}

// ---------------------------------------------------------------------------
// Stats kernel: register-resident; moments + top-409 |x| sum via 2-pass radix
// (16 prefix bits + threshold correction). Fused k-predictor.
// ---------------------------------------------------------------------------
__global__ void stats_kernel(const float* __restrict__ x, float* __restrict__ stats,
                             const float* __restrict__ Wk1, const float* __restrict__ bk1,
                             const float* __restrict__ Wk2, const float* __restrict__ bk2)
{
    __shared__ float red[48];
    __shared__ float sres[8];
    __shared__ int hist[256];
    __shared__ int warptot[8];
    __shared__ unsigned s_pref;
    __shared__ int s_need;

    int row = blockIdx.x;
    int tid = threadIdx.x;
    int lane = tid & 31, w = tid >> 5;

    const float4* xr = (const float4*)(x + (size_t)row * DD);
    float4 a4 = xr[tid * 2], b4 = xr[tid * 2 + 1];
    float v[8] = {a4.x, a4.y, a4.z, a4.w, b4.x, b4.y, b4.z, b4.w};
    unsigned bb[8];
#pragma unroll
    for (int j = 0; j < 8; ++j) bb[j] = __float_as_uint(v[j]) & 0x7fffffffu;

    float sum = 0.f, sumsq = 0.f, suma = 0.f, zc = 0.f, maxa = 0.f;
#pragma unroll
    for (int j = 0; j < 8; ++j) {
        float vv = v[j];
        sum += vv; sumsq += vv * vv;
        float ab = fabsf(vv);
        suma += ab; maxa = fmaxf(maxa, ab);
        zc += (vv == 0.0f) ? 1.f : 0.f;
    }
#pragma unroll
    for (int o = 16; o; o >>= 1) {
        sum   += __shfl_down_sync(0xffffffffu, sum,   o);
        sumsq += __shfl_down_sync(0xffffffffu, sumsq, o);
        suma  += __shfl_down_sync(0xffffffffu, suma,  o);
        zc    += __shfl_down_sync(0xffffffffu, zc,    o);
        maxa   = fmaxf(maxa, __shfl_down_sync(0xffffffffu, maxa, o));
    }
    if (lane == 0) {
        red[w * 5 + 0] = sum;  red[w * 5 + 1] = sumsq; red[w * 5 + 2] = suma;
        red[w * 5 + 3] = zc;   red[w * 5 + 4] = maxa;
    }
    __syncthreads();
    if (tid < 5) {
        float r0 = red[tid];
        if (tid < 4) { for (int w2 = 1; w2 < 8; ++w2) r0 += red[w2 * 5 + tid]; }
        else         { for (int w2 = 1; w2 < 8; ++w2) r0 = fmaxf(r0, red[w2 * 5 + tid]); }
        sres[tid] = r0;
    }
    __syncthreads();
    sum = sres[0]; sumsq = sres[1]; suma = sres[2]; zc = sres[3]; maxa = sres[4];
    float mean = sum * (1.0f / 2048.0f);

    float s2 = 0.f, s3 = 0.f;
#pragma unroll
    for (int j = 0; j < 8; ++j) {
        float d = v[j] - mean;
        s2 += d * d;
        s3 += d * d * d;
    }
#pragma unroll
    for (int o = 16; o; o >>= 1) {
        s2 += __shfl_down_sync(0xffffffffu, s2, o);
        s3 += __shfl_down_sync(0xffffffffu, s3, o);
    }
    __syncthreads();
    if (lane == 0) { red[w * 2 + 0] = s2; red[w * 2 + 1] = s3; }
    __syncthreads();
    if (tid < 2) {
        float r0 = red[tid];
        for (int w2 = 1; w2 < 8; ++w2) r0 += red[w2 * 2 + tid];
        sres[5 + tid] = r0;
    }
    __syncthreads();
    s2 = sres[5]; s3 = sres[6];
    float var  = s2 * (1.0f / 2047.0f);
    float stdv = sqrtf(var + 1e-8f);
    float skew = (s3 * (1.0f / 2048.0f)) / (stdv * stdv * stdv);

    unsigned prefix = 0;
    int need = TOPC;
#pragma unroll
    for (int pass = 0; pass < 2; ++pass) {
        int shift = (pass == 0) ? 23 : 15;
        hist[tid] = 0;
        __syncthreads();
#pragma unroll
        for (int j = 0; j < 8; ++j) {
            bool match = (pass == 0) || ((bb[j] >> 23) == prefix);
            unsigned bin = (bb[j] >> shift) & 255;
            unsigned key = match ? bin : 0xffffffffu;
            unsigned grp = __match_any_sync(0xffffffffu, key);
            int leader = __ffs(grp) - 1;
            if (match && lane == leader)
                atomicAdd(&hist[bin], __popc(grp));
        }
        __syncthreads();
        int h = hist[tid];
        int suf = h;
#pragma unroll
        for (int o = 1; o < 32; o <<= 1) {
            int t = __shfl_down_sync(0xffffffffu, suf, o);
            if (lane + o < 32) suf += t;
        }
        if (lane == 0) warptot[w] = suf;
        __syncthreads();
        int tail = 0;
#pragma unroll
        for (int w2 = 0; w2 < 8; ++w2)
            if (w2 > w) tail += warptot[w2];
        int incl = suf + tail;
        int excl = incl - h;
        if (excl < need && need <= incl) {
            s_pref = (prefix << 8) | (unsigned)tid;
            s_need = need - excl;
        }
        __syncthreads();
        prefix = s_pref;
        need = s_need;
        __syncthreads();
    }

    unsigned tb = prefix << 15;
    float tsum = 0.f;
    int tcnt = 0;
#pragma unroll
    for (int j = 0; j < 8; ++j)
        if (bb[j] >= tb) { tsum += __uint_as_float(bb[j]); tcnt++; }
#pragma unroll
    for (int o = 16; o; o >>= 1) {
        tsum += __shfl_down_sync(0xffffffffu, tsum, o);
        tcnt += __shfl_down_sync(0xffffffffu, tcnt, o);
    }
    if (lane == 0) { red[w] = tsum; warptot[w] = tcnt; }
    __syncthreads();
    if (tid == 0) {
        float tt = 0.f; int nc = 0;
        for (int w2 = 0; w2 < 8; ++w2) { tt += red[w2]; nc += warptot[w2]; }
        float tmid = __uint_as_float(tb + (1u << 14));
        tt -= (float)(nc - TOPC) * tmid;
        float st[6];
        st[0] = zc * (1.0f / 2048.0f);
        st[1] = var;
        st[2] = maxa;
        st[3] = sqrtf(sumsq);
        st[4] = skew;
        st[5] = tt / (suma + 1e-8f);
        float* o = stats + (size_t)row * 6;
#pragma unroll
        for (int i = 0; i < 6; ++i) o[i] = st[i];

        float kp = bk2[0];
#pragma unroll
        for (int hh = 0; hh < 16; ++hh) {
            float z = bk1[hh];
#pragma unroll
            for (int i = 0; i < 6; ++i) z += st[i] * Wk1[i * 16 + hh];
            kp += fmaxf(z, 0.f) * Wk2[hh];
        }
        float kv = 1.0f / (1.0f + expf(-kp));
        float val = 1.0f + 3.0f * kv;
        if (val < 2.0f) atomicAdd(&g_cnt[0], 1);
        if (val < 3.0f) atomicAdd(&g_cnt[1], 1);
        if (val < 4.0f) atomicAdd(&g_cnt[2], 1);
    }
}

// ---------------------------------------------------------------------------
// sims kernel: sims = x @ patterns^T   (independent of GEMM chain)
// ---------------------------------------------------------------------------
__global__ void sims_kernel(const float* __restrict__ x, const float* __restrict__ pat,
                            float* __restrict__ sims)
{
    __shared__ float xs[64][68];
    __shared__ float ws[64][16];
    int tid = threadIdx.x;
    int row0 = blockIdx.x * 64;
    int e = tid & 15;
    int r0 = (tid >> 4) * 4;
    float acc[4] = {};

    for (int kc = 0; kc < DD; kc += 64) {
#pragma unroll
        for (int it = 0; it < 4; ++it) {
            int idx = tid + it * 256;
            int r = idx >> 4, c4 = idx & 15;
            *(float4*)&xs[r][c4 * 4] =
                *(const float4*)(x + (size_t)(row0 + r) * DD + kc + c4 * 4);
        }
        {
            int pe = tid & 15, k4 = tid >> 4;
            float4 v = *(const float4*)(pat + (size_t)pe * DD + kc + k4 * 4);
            ws[k4 * 4 + 0][pe] = v.x; ws[k4 * 4 + 1][pe] = v.y;
            ws[k4 * 4 + 2][pe] = v.z; ws[k4 * 4 + 3][pe] = v.w;
        }
        __syncthreads();
#pragma unroll 4
        for (int k = 0; k < 64; ++k) {
            float wv = ws[k][e];
            acc[0] += xs[r0 + 0][k] * wv;
            acc[1] += xs[r0 + 1][k] * wv;
            acc[2] += xs[r0 + 2][k] * wv;
            acc[3] += xs[r0 + 3][k] * wv;
        }
        __syncthreads();
    }
#pragma unroll
    for (int j = 0; j < 4; ++j)
        sims[(size_t)(row0 + r0 + j) * EE + e] = acc[j];
}

// ---------------------------------------------------------------------------
// spec2 kernel: spec = sigmoid(sims + h1@Ws2 + bs2); writes bf16 split of
// spec into xT rows [2048, 2064)
// ---------------------------------------------------------------------------
__global__ void spec2_kernel(const float* __restrict__ sims,
                             const float* __restrict__ h1, const float* __restrict__ Ws2,
                             const float* __restrict__ bs2, float* __restrict__ spec,
                             __nv_bfloat16* __restrict__ xth, __nv_bfloat16* __restrict__ xtl)
{
    __shared__ float xs[64][68];
    __shared__ float ws[64][16];
    int tid = threadIdx.x;
    int row0 = blockIdx.x * 64;
    int e = tid & 15;
    int r0 = (tid >> 4) * 4;
    float acc[4];
#pragma unroll
    for (int j = 0; j < 4; ++j)
        acc[j] = sims[(size_t)(row0 + r0 + j) * EE + e];

    for (int kc = 0; kc < HH; kc += 64) {
#pragma unroll
        for (int it = 0; it < 4; ++it) {
            int idx = tid + it * 256;
            int r = idx >> 4, c4 = idx & 15;
            *(float4*)&xs[r][c4 * 4] =
                *(const float4*)(h1 + (size_t)(row0 + r) * HH + kc + c4 * 4);
        }
        {
            int k = tid >> 2, e4 = tid & 3;
            *(float4*)&ws[k][e4 * 4] =
                *(const float4*)(Ws2 + (size_t)(kc + k) * EE + e4 * 4);
        }
        __syncthreads();
#pragma unroll 4
        for (int k = 0; k < 64; ++k) {
            float wv = ws[k][e];
            acc[0] += xs[r0 + 0][k] * wv;
            acc[1] += xs[r0 + 1][k] * wv;
            acc[2] += xs[r0 + 2][k] * wv;
            acc[3] += xs[r0 + 3][k] * wv;
        }
        __syncthreads();
    }
    float b = bs2[e];
#pragma unroll
    for (int j = 0; j < 4; ++j) {
        float vv = acc[j] + b;
        float sg = 1.0f / (1.0f + expf(-vv));
        size_t row = (size_t)(row0 + r0 + j);
        spec[row * EE + e] = sg;
        __nv_bfloat16 h = __float2bfloat16(sg);
        xth[(size_t)(DD + e) * BB + row] = h;
        xtl[(size_t)(DD + e) * BB + row] = __float2bfloat16(sg - __bfloat162float(h));
    }
}

// ---------------------------------------------------------------------------
// probs + topk fused: probs = softmax(h2 @ Wr2 + br2); then top-4 + gates.
// ---------------------------------------------------------------------------
__global__ void probs_topk_kernel(const float* __restrict__ h2, const float* __restrict__ Wr2,
                                  const float* __restrict__ br2, float* __restrict__ probs,
                                  float* __restrict__ gates, float* __restrict__ idxo)
{
    __shared__ float xs[64][68];
    __shared__ float ws[64][16];
    __shared__ float lg[64][17];
    int tid = threadIdx.x;
    int row0 = blockIdx.x * 64;
    int e = tid & 15;
    int r0 = (tid >> 4) * 4;
    float acc[4] = {};

    for (int kc = 0; kc < HH; kc += 64) {
#pragma unroll
        for (int it = 0; it < 4; ++it) {
            int idx = tid + it * 256;
            int r = idx >> 4, c4 = idx & 15;
            *(float4*)&xs[r][c4 * 4] =
                *(const float4*)(h2 + (size_t)(row0 + r) * HH + kc + c4 * 4);
        }
        {
            int k = tid >> 2, e4 = tid & 3;
            *(float4*)&ws[k][e4 * 4] =
                *(const float4*)(Wr2 + (size_t)(kc + k) * EE + e4 * 4);
        }
        __syncthreads();
#pragma unroll 4
        for (int k = 0; k < 64; ++k) {
            float wv = ws[k][e];
            acc[0] += xs[r0 + 0][k] * wv;
            acc[1] += xs[r0 + 1][k] * wv;
            acc[2] += xs[r0 + 2][k] * wv;
            acc[3] += xs[r0 + 3][k] * wv;
        }
        __syncthreads();
    }
    float b = br2[e];
#pragma unroll
    for (int j = 0; j < 4; ++j) lg[r0 + j][e] = acc[j] + b;
    __syncthreads();

    if (tid < 64) {
        int r = tid;
        int row = row0 + r;
        float m = -3.4e38f;
#pragma unroll
        for (int k = 0; k < 16; ++k) m = fmaxf(m, lg[r][k]);
        float pv[16]; float s = 0.f;
#pragma unroll
        for (int k = 0; k < 16; ++k) { pv[k] = expf(lg[r][k] - m); s += pv[k]; }
        float inv = 1.0f / s;
#pragma unroll
        for (int k = 0; k < 16; ++k) pv[k] *= inv;
        float* o = probs + (size_t)row * EE;
#pragma unroll
        for (int k = 0; k < 16; ++k) o[k] = pv[k];

        // top-4 + gates
        int c0 = g_cnt[0], c1 = g_cnt[1], c2 = g_cnt[2];
        int kk = (c0 >= 8192) ? 1 : (c1 >= 8192) ? 2 : (c2 >= 8192) ? 3 : 4;

        unsigned used = 0;
        float tv[4]; int ti[4];
#pragma unroll
        for (int s4 = 0; s4 < 4; ++s4) {
            float bv = -1.0f; int bi = 0;
#pragma unroll
            for (int e2 = 0; e2 < 16; ++e2) {
                bool ok = (((used >> e2) & 1u) == 0u) && (pv[e2] > bv);
                if (ok) { bv = pv[e2]; bi = e2; }
            }
            used |= (1u << bi);
            tv[s4] = bv; ti[s4] = bi;
        }
        float gg[4]; float ssum = 0.f;
#pragma unroll
        for (int j = 0; j < 4; ++j) {
            gg[j] = (j < kk) ? expf(tv[j] - tv[0]) : 0.0f;
            ssum += gg[j];
        }
        float ginv = 1.0f / ssum;
#pragma unroll
        for (int j = 0; j < 4; ++j) {
            gates[(size_t)row * 4 + j] = gg[j] * ginv;
            idxo[(size_t)row * 4 + j] = (float)ti[j];
        }
    }
}

// ---------------------------------------------------------------------------
__global__ void init_kernel() { g_cnt[0] = 0; g_cnt[1] = 0; g_cnt[2] = 0; }

// ---------------------------------------------------------------------------
extern "C" void kernel_launch(void* const* d_in, const int* in_sizes, int n_in,
                              void* d_out, int out_size)
{
    const float* x    = (const float*)d_in[0];
    const float* pat  = (const float*)d_in[1];
    const float* Ws1  = (const float*)d_in[2];
    const float* bs1  = (const float*)d_in[3];
    const float* Ws2  = (const float*)d_in[4];
    const float* bs2  = (const float*)d_in[5];
    const float* Wr1  = (const float*)d_in[6];
    const float* br1  = (const float*)d_in[7];
    const float* Wr2  = (const float*)d_in[8];
    const float* br2  = (const float*)d_in[9];
    const float* Wk1  = (const float*)d_in[10];
    const float* bk1  = (const float*)d_in[11];
    const float* Wk2  = (const float*)d_in[12];
    const float* bk2  = (const float*)d_in[13];

    float* out = (float*)d_out;
    float* o_gates = out;                      // 16384*4
    float* o_idx   = out + 65536;              // 16384*4
    float* o_probs = out + 131072;             // 16384*16
    float* o_stats = out + 393216;             // 16384*6

    void* p;
    cudaGetSymbolAddress(&p, g_h1);   float* h1 = (float*)p;
    cudaGetSymbolAddress(&p, g_h2);   float* h2 = (float*)p;
    cudaGetSymbolAddress(&p, g_spec); float* spec = (float*)p;
    cudaGetSymbolAddress(&p, g_sims); float* sims = (float*)p;
    cudaGetSymbolAddress(&p, g_xth);  __nv_bfloat16* xth = (__nv_bfloat16*)p;
    cudaGetSymbolAddress(&p, g_xtl);  __nv_bfloat16* xtl = (__nv_bfloat16*)p;
    cudaGetSymbolAddress(&p, g_w1h);  __nv_bfloat16* w1h = (__nv_bfloat16*)p;
    cudaGetSymbolAddress(&p, g_w1l);  __nv_bfloat16* w1l = (__nv_bfloat16*)p;
    cudaGetSymbolAddress(&p, g_w2h);  __nv_bfloat16* w2h = (__nv_bfloat16*)p;
    cudaGetSymbolAddress(&p, g_w2l);  __nv_bfloat16* w2l = (__nv_bfloat16*)p;

    cudaFuncSetAttribute(gemm_mma, cudaFuncAttributeMaxDynamicSharedMemorySize, GEMM_SMEM);

    // side stream + fork/join events (created once; identical topology per call)
    static cudaStream_t s1 = 0;
    static cudaEvent_t evF = 0, evW = 0, evA = 0, evB = 0;
    if (evB == 0) {
        cudaStreamCreateWithFlags(&s1, cudaStreamNonBlocking);
        cudaEventCreateWithFlags(&evF, cudaEventDisableTiming);
        cudaEventCreateWithFlags(&evW, cudaEventDisableTiming);
        cudaEventCreateWithFlags(&evA, cudaEventDisableTiming);
        cudaEventCreateWithFlags(&evB, cudaEventDisableTiming);
    }

    // fork s1 from the main (default) stream
    cudaEventRecord(evF, 0);
    cudaStreamWaitEvent(s1, evF, 0);

    // ---- s1: independent work (hidden under split_xT / GEMM1) ----
    init_kernel<<<1, 1, 0, s1>>>();
    split_w_kernel<<<(KTOT * HH) / 256, 256, 0, s1>>>(Ws1, DD, w1h, w1l);
    cudaEventRecord(evW, s1);                    // w1 ready
    split_w_kernel<<<(KTOT * HH) / 256, 256, 0, s1>>>(Wr1, DD + EE, w2h, w2l);
    sims_kernel<<<BB / 64, 256, 0, s1>>>(x, pat, sims);
    cudaEventRecord(evA, s1);                    // sims + w2 ready
    stats_kernel<<<BB, 256, 0, s1>>>(x, o_stats, Wk1, bk1, Wk2, bk2);
    cudaEventRecord(evB, s1);                    // stats/g_cnt ready

    // ---- s0 (default stream): GEMM chain ----
    {
        dim3 tg(KTOT / 32, BB / 64);
        split_xT_kernel<<<tg, 256>>>(x, xth, xtl);
    }

    dim3 gg(HH / 128, BB / 128);
    cudaStreamWaitEvent(0, evW, 0);              // need w1h/w1l
    gemm_mma<<<gg, 256, GEMM_SMEM>>>(xth, xtl, w1h, w1l, bs1, h1, 64);

    cudaStreamWaitEvent(0, evA, 0);              // need sims + w2h/w2l
    spec2_kernel<<<BB / 64, 256>>>(sims, h1, Ws2, bs2, spec, xth, xtl);

    gemm_mma<<<gg, 256, GEMM_SMEM>>>(xth, xtl, w2h, w2l, br1, h2, 65);

    cudaStreamWaitEvent(0, evB, 0);              // need g_cnt
    probs_topk_kernel<<<BB / 64, 256>>>(h2, Wr2, br2, o_probs, o_gates, o_idx);

    (void)in_sizes; (void)n_in; (void)out_size;
}

// round 10
// speedup vs baseline: 1.0055x; 1.0055x over previous
#include <cuda_runtime.h>
#include <cuda_bf16.h>
#include <cstdint>

// Problem constants (fixed shapes)
#define BB 16384
#define DD 2048
#define HH 1024
#define EE 16
#define TOPC 409
#define KTOT 2080          // padded K: 2048 + 16 (spec) + 16 pad, %32==0

// ---------------------------------------------------------------------------
// Device global scratch (no runtime allocation allowed)
// ---------------------------------------------------------------------------
__device__ float g_h1[(size_t)BB * HH];
__device__ float g_h2[(size_t)BB * HH];
__device__ float g_spec[(size_t)BB * EE];
__device__ float g_sims[(size_t)BB * EE];
__device__ __nv_bfloat16 g_xth[(size_t)KTOT * BB];   // x^T hi, k-major [K][B]
__device__ __nv_bfloat16 g_xtl[(size_t)KTOT * BB];   // x^T lo
__device__ __nv_bfloat16 g_w1h[(size_t)KTOT * HH];
__device__ __nv_bfloat16 g_w1l[(size_t)KTOT * HH];
__device__ __nv_bfloat16 g_w2h[(size_t)KTOT * HH];
__device__ __nv_bfloat16 g_w2l[(size_t)KTOT * HH];
__device__ int g_cnt[3];

// ---------------------------------------------------------------------------
// helpers
// ---------------------------------------------------------------------------
__device__ __forceinline__ uint32_t smem_u32(const void* p) {
    uint32_t a;
    asm("{ .reg .u64 t; cvta.to.shared.u64 t, %1; cvt.u32.u64 %0, t; }" : "=r"(a) : "l"(p));
    return a;
}

#define CPA16(dst, src) \
    asm volatile("cp.async.cg.shared.global [%0], [%1], 16;" :: "r"(dst), "l"(src))
#define CPA_COMMIT() asm volatile("cp.async.commit_group;" ::: "memory")

#define LDSM4T(r0, r1, r2, r3, addr) \
    asm volatile("ldmatrix.sync.aligned.m8n8.x4.trans.shared.b16 {%0,%1,%2,%3}, [%4];" \
                 : "=r"(r0), "=r"(r1), "=r"(r2), "=r"(r3) : "r"(addr) : "memory")

#define MMA16816(d, a, b0, b1) \
    asm volatile("mma.sync.aligned.m16n8k16.row.col.f32.bf16.bf16.f32 " \
                 "{%0,%1,%2,%3}, {%4,%5,%6,%7}, {%8,%9}, {%0,%1,%2,%3};" \
                 : "+f"((d)[0]), "+f"((d)[1]), "+f"((d)[2]), "+f"((d)[3]) \
                 : "r"((a)[0]), "r"((a)[1]), "r"((a)[2]), "r"((a)[3]), \
                   "r"(b0), "r"(b1))

// ---------------------------------------------------------------------------
// split + transpose x: [B, D] fp32 -> xT hi/lo bf16 [KTOT][B]; zero k>=2048.
// ---------------------------------------------------------------------------
__global__ void split_xT_kernel(const float* __restrict__ x,
                                __nv_bfloat16* __restrict__ xh,
                                __nv_bfloat16* __restrict__ xl)
{
    __shared__ float t[64][33];
    int k0 = blockIdx.x * 32;        // 65 tiles
    int m0 = blockIdx.y * 64;        // 256 tiles
    int tid = threadIdx.x;

    int k = tid >> 3;                // 0..31
    int mm = (tid & 7) * 8;          // 0..56

    if (k0 < DD) {
        int r = tid >> 2;            // 0..63
        int c = (tid & 3) * 8;       // 0,8,16,24
        const float* src = x + (size_t)(m0 + r) * DD + k0 + c;
        float4 v0 = *(const float4*)src;
        float4 v1 = *(const float4*)(src + 4);
        t[r][c + 0] = v0.x; t[r][c + 1] = v0.y; t[r][c + 2] = v0.z; t[r][c + 3] = v0.w;
        t[r][c + 4] = v1.x; t[r][c + 5] = v1.y; t[r][c + 6] = v1.z; t[r][c + 7] = v1.w;
        __syncthreads();

        __nv_bfloat16 h8[8], l8[8];
#pragma unroll
        for (int j = 0; j < 8; ++j) {
            float v = t[mm + j][k];
            __nv_bfloat16 h = __float2bfloat16(v);
            h8[j] = h;
            l8[j] = __float2bfloat16(v - __bfloat162float(h));
        }
        *(uint4*)(xh + (size_t)(k0 + k) * BB + m0 + mm) = *(uint4*)h8;
        *(uint4*)(xl + (size_t)(k0 + k) * BB + m0 + mm) = *(uint4*)l8;
    } else {
        uint4 z = {0, 0, 0, 0};
        *(uint4*)(xh + (size_t)(k0 + k) * BB + m0 + mm) = z;
        *(uint4*)(xl + (size_t)(k0 + k) * BB + m0 + mm) = z;
    }
}

// ---------------------------------------------------------------------------
// split W: [Klim, 1024] fp32 -> hi/lo bf16 [KTOT][1024], zero past Klim
// ---------------------------------------------------------------------------
__global__ void split_w_kernel(const float* __restrict__ W, int Klim,
                               __nv_bfloat16* __restrict__ wh,
                               __nv_bfloat16* __restrict__ wl)
{
    int idx = blockIdx.x * 256 + threadIdx.x;   // over KTOT*1024
    int k = idx >> 10, n = idx & 1023;
    float v = (k < Klim) ? W[(size_t)k * HH + n] : 0.0f;
    __nv_bfloat16 h = __float2bfloat16(v);
    wh[idx] = h;
    wl[idx] = __float2bfloat16(v - __bfloat162float(h));
}

// ---------------------------------------------------------------------------
// HMMA split-bf16 GEMM (round-4/8 proven version): BK=32, 2-stage cp.async.
// CTA tile 128x128, 8 warps (2m x 4n), each warp 64x32. 2 CTAs/SM.
// ---------------------------------------------------------------------------
#define STG_BYTES 32768
#define GEMM_SMEM (2 * STG_BYTES + 1024)

__device__ __forceinline__ void gemm_ld_stage(
    uint32_t db, int s, int c,
    const __nv_bfloat16* __restrict__ Ah, const __nv_bfloat16* __restrict__ Al,
    const __nv_bfloat16* __restrict__ Wh, const __nv_bfloat16* __restrict__ Wl,
    int m0, int n0, int tid)
{
    int k  = tid >> 3;                 // 0..31
    int mc = (tid & 7) * 2;            // chunk pair
    uint32_t base = db + s * STG_BYTES;
    uint32_t d0 = k * 256 + ((mc ^ (k & 7)) << 4);
    uint32_t d1 = k * 256 + (((mc + 1) ^ (k & 7)) << 4);
    size_t ka = (size_t)(c * 32 + k);
    const char* pah = (const char*)(Ah + ka * BB + m0 + mc * 8);
    const char* pal = (const char*)(Al + ka * BB + m0 + mc * 8);
    const char* pwh = (const char*)(Wh + ka * HH + n0 + mc * 8);
    const char* pwl = (const char*)(Wl + ka * HH + n0 + mc * 8);
    CPA16(base + d0,         pah);      CPA16(base + d1,         pah + 16);
    CPA16(base + 8192  + d0, pal);      CPA16(base + 8192  + d1, pal + 16);
    CPA16(base + 16384 + d0, pwh);      CPA16(base + 16384 + d1, pwh + 16);
    CPA16(base + 24576 + d0, pwl);      CPA16(base + 24576 + d1, pwl + 16);
    CPA_COMMIT();
}

__global__ __launch_bounds__(256, 1)
void gemm_mma(const __nv_bfloat16* __restrict__ Ah, const __nv_bfloat16* __restrict__ Al,
              const __nv_bfloat16* __restrict__ Wh, const __nv_bfloat16* __restrict__ Wl,
              const float* __restrict__ bias, float* __restrict__ C, int nch)
{
    extern __shared__ char smem[];
    uint32_t db = (smem_u32(smem) + 1023) & ~1023u;
    int tid = threadIdx.x, lane = tid & 31, wid = tid >> 5;
    int wm = wid >> 2, wn = wid & 3;
    int m0 = blockIdx.y * 128, n0 = blockIdx.x * 128;

    int q = lane >> 3, r = lane & 7;
    int kq = ((q >> 1) << 3) + r;       // 0..15
    int sw = kq & 7;
    uint32_t offA[4], offB[2];
#pragma unroll
    for (int mt = 0; mt < 4; ++mt) {
        int cc = wm * 8 + mt * 2 + (q & 1);
        offA[mt] = kq * 256 + ((cc ^ sw) << 4);
    }
#pragma unroll
    for (int bt = 0; bt < 2; ++bt) {
        int cc = wn * 4 + bt * 2 + (q & 1);
        offB[bt] = kq * 256 + ((cc ^ sw) << 4);
    }

    float acc[4][4][4] = {};

    gemm_ld_stage(db, 0, 0, Ah, Al, Wh, Wl, m0, n0, tid);

    for (int c = 0; c < nch; ++c) {
        if (c + 1 < nch) {
            gemm_ld_stage(db, (c + 1) & 1, c + 1, Ah, Al, Wh, Wl, m0, n0, tid);
            asm volatile("cp.async.wait_group 1;" ::: "memory");
        } else {
            asm volatile("cp.async.wait_group 0;" ::: "memory");
        }
        __syncthreads();

        uint32_t sbase = db + (c & 1) * STG_BYTES;
#pragma unroll
        for (int ks = 0; ks < 2; ++ks) {
            uint32_t sb = sbase + ks * 4096;
            uint32_t ah[4][4], al_[4][4], bh_[2][4], bl_[2][4];
#pragma unroll
            for (int mt = 0; mt < 4; ++mt) {
                LDSM4T(ah[mt][0],  ah[mt][1],  ah[mt][2],  ah[mt][3],  sb + offA[mt]);
                LDSM4T(al_[mt][0], al_[mt][1], al_[mt][2], al_[mt][3], sb + 8192 + offA[mt]);
            }
#pragma unroll
            for (int bt = 0; bt < 2; ++bt) {
                LDSM4T(bh_[bt][0], bh_[bt][1], bh_[bt][2], bh_[bt][3], sb + 16384 + offB[bt]);
                LDSM4T(bl_[bt][0], bl_[bt][1], bl_[bt][2], bl_[bt][3], sb + 24576 + offB[bt]);
            }
#pragma unroll
            for (int mt = 0; mt < 4; ++mt)
#pragma unroll
                for (int nt = 0; nt < 4; ++nt) {
                    int bt = nt >> 1, p = nt & 1;
                    MMA16816(acc[mt][nt], ah[mt], bh_[bt][p], bh_[bt][p + 2]);
                }
#pragma unroll
            for (int mt = 0; mt < 4; ++mt)
#pragma unroll
                for (int nt = 0; nt < 4; ++nt) {
                    int bt = nt >> 1, p = nt & 1;
                    MMA16816(acc[mt][nt], ah[mt], bl_[bt][p], bl_[bt][p + 2]);
                }
#pragma unroll
            for (int mt = 0; mt < 4; ++mt)
#pragma unroll
                for (int nt = 0; nt < 4; ++nt) {
                    int bt = nt >> 1, p = nt & 1;
                    MMA16816(acc[mt][nt], al_[mt], bh_[bt][p], bh_[bt][p + 2]);
                }
        }
        __syncthreads();
    }

    int g = lane >> 2, t2 = (lane & 3) * 2;
#pragma unroll
    for (int nt = 0; nt < 4; ++nt) {
        int col = n0 + wn * 32 + nt * 8 + t2;
        float2 bv = *(const float2*)(bias + col);
#pragma unroll
        for (int mt = 0; mt < 4; ++mt) {
            int row = m0 + wm * 64 + mt * 16 + g;
            float2 o0, o1;
            o0.x = fmaxf(acc[mt][nt][0] + bv.x, 0.f);
            o0.y = fmaxf(acc[mt][nt][1] + bv.y, 0.f);
            o1.x = fmaxf(acc[mt][nt][2] + bv.x, 0.f);
            o1.y = fmaxf(acc[mt][nt][3] + bv.y, 0.f);
            *(float2*)(C + (size_t)row * HH + col) = o0;
            *(float2*)(C + (size_t)(row + 8) * HH + col) = o1;
        }
    }
}

// ---------------------------------------------------------------------------
// Stats kernel: register-resident; moments + top-409 |x| sum via 2-pass radix
// (16 prefix bits + threshold correction). Fused k-predictor.
// ---------------------------------------------------------------------------
__global__ void stats_kernel(const float* __restrict__ x, float* __restrict__ stats,
                             const float* __restrict__ Wk1, const float* __restrict__ bk1,
                             const float* __restrict__ Wk2, const float* __restrict__ bk2)
{
    __shared__ float red[48];
    __shared__ float sres[8];
    __shared__ int hist[256];
    __shared__ int warptot[8];
    __shared__ unsigned s_pref;
    __shared__ int s_need;

    int row = blockIdx.x;
    int tid = threadIdx.x;
    int lane = tid & 31, w = tid >> 5;

    const float4* xr = (const float4*)(x + (size_t)row * DD);
    float4 a4 = xr[tid * 2], b4 = xr[tid * 2 + 1];
    float v[8] = {a4.x, a4.y, a4.z, a4.w, b4.x, b4.y, b4.z, b4.w};
    unsigned bb[8];
#pragma unroll
    for (int j = 0; j < 8; ++j) bb[j] = __float_as_uint(v[j]) & 0x7fffffffu;

    float sum = 0.f, sumsq = 0.f, suma = 0.f, zc = 0.f, maxa = 0.f;
#pragma unroll
    for (int j = 0; j < 8; ++j) {
        float vv = v[j];
        sum += vv; sumsq += vv * vv;
        float ab = fabsf(vv);
        suma += ab; maxa = fmaxf(maxa, ab);
        zc += (vv == 0.0f) ? 1.f : 0.f;
    }
#pragma unroll
    for (int o = 16; o; o >>= 1) {
        sum   += __shfl_down_sync(0xffffffffu, sum,   o);
        sumsq += __shfl_down_sync(0xffffffffu, sumsq, o);
        suma  += __shfl_down_sync(0xffffffffu, suma,  o);
        zc    += __shfl_down_sync(0xffffffffu, zc,    o);
        maxa   = fmaxf(maxa, __shfl_down_sync(0xffffffffu, maxa, o));
    }
    if (lane == 0) {
        red[w * 5 + 0] = sum;  red[w * 5 + 1] = sumsq; red[w * 5 + 2] = suma;
        red[w * 5 + 3] = zc;   red[w * 5 + 4] = maxa;
    }
    __syncthreads();
    if (tid < 5) {
        float r0 = red[tid];
        if (tid < 4) { for (int w2 = 1; w2 < 8; ++w2) r0 += red[w2 * 5 + tid]; }
        else         { for (int w2 = 1; w2 < 8; ++w2) r0 = fmaxf(r0, red[w2 * 5 + tid]); }
        sres[tid] = r0;
    }
    __syncthreads();
    sum = sres[0]; sumsq = sres[1]; suma = sres[2]; zc = sres[3]; maxa = sres[4];
    float mean = sum * (1.0f / 2048.0f);

    float s2 = 0.f, s3 = 0.f;
#pragma unroll
    for (int j = 0; j < 8; ++j) {
        float d = v[j] - mean;
        s2 += d * d;
        s3 += d * d * d;
    }
#pragma unroll
    for (int o = 16; o; o >>= 1) {
        s2 += __shfl_down_sync(0xffffffffu, s2, o);
        s3 += __shfl_down_sync(0xffffffffu, s3, o);
    }
    __syncthreads();
    if (lane == 0) { red[w * 2 + 0] = s2; red[w * 2 + 1] = s3; }
    __syncthreads();
    if (tid < 2) {
        float r0 = red[tid];
        for (int w2 = 1; w2 < 8; ++w2) r0 += red[w2 * 2 + tid];
        sres[5 + tid] = r0;
    }
    __syncthreads();
    s2 = sres[5]; s3 = sres[6];
    float var  = s2 * (1.0f / 2047.0f);
    float stdv = sqrtf(var + 1e-8f);
    float skew = (s3 * (1.0f / 2048.0f)) / (stdv * stdv * stdv);

    unsigned prefix = 0;
    int need = TOPC;
#pragma unroll
    for (int pass = 0; pass < 2; ++pass) {
        int shift = (pass == 0) ? 23 : 15;
        hist[tid] = 0;
        __syncthreads();
#pragma unroll
        for (int j = 0; j < 8; ++j) {
            bool match = (pass == 0) || ((bb[j] >> 23) == prefix);
            unsigned bin = (bb[j] >> shift) & 255;
            unsigned key = match ? bin : 0xffffffffu;
            unsigned grp = __match_any_sync(0xffffffffu, key);
            int leader = __ffs(grp) - 1;
            if (match && lane == leader)
                atomicAdd(&hist[bin], __popc(grp));
        }
        __syncthreads();
        int h = hist[tid];
        int suf = h;
#pragma unroll
        for (int o = 1; o < 32; o <<= 1) {
            int t = __shfl_down_sync(0xffffffffu, suf, o);
            if (lane + o < 32) suf += t;
        }
        if (lane == 0) warptot[w] = suf;
        __syncthreads();
        int tail = 0;
#pragma unroll
        for (int w2 = 0; w2 < 8; ++w2)
            if (w2 > w) tail += warptot[w2];
        int incl = suf + tail;
        int excl = incl - h;
        if (excl < need && need <= incl) {
            s_pref = (prefix << 8) | (unsigned)tid;
            s_need = need - excl;
        }
        __syncthreads();
        prefix = s_pref;
        need = s_need;
        __syncthreads();
    }

    unsigned tb = prefix << 15;
    float tsum = 0.f;
    int tcnt = 0;
#pragma unroll
    for (int j = 0; j < 8; ++j)
        if (bb[j] >= tb) { tsum += __uint_as_float(bb[j]); tcnt++; }
#pragma unroll
    for (int o = 16; o; o >>= 1) {
        tsum += __shfl_down_sync(0xffffffffu, tsum, o);
        tcnt += __shfl_down_sync(0xffffffffu, tcnt, o);
    }
    if (lane == 0) { red[w] = tsum; warptot[w] = tcnt; }
    __syncthreads();
    if (tid == 0) {
        float tt = 0.f; int nc = 0;
        for (int w2 = 0; w2 < 8; ++w2) { tt += red[w2]; nc += warptot[w2]; }
        float tmid = __uint_as_float(tb + (1u << 14));
        tt -= (float)(nc - TOPC) * tmid;
        float st[6];
        st[0] = zc * (1.0f / 2048.0f);
        st[1] = var;
        st[2] = maxa;
        st[3] = sqrtf(sumsq);
        st[4] = skew;
        st[5] = tt / (suma + 1e-8f);
        float* o = stats + (size_t)row * 6;
#pragma unroll
        for (int i = 0; i < 6; ++i) o[i] = st[i];

        float kp = bk2[0];
#pragma unroll
        for (int hh = 0; hh < 16; ++hh) {
            float z = bk1[hh];
#pragma unroll
            for (int i = 0; i < 6; ++i) z += st[i] * Wk1[i * 16 + hh];
            kp += fmaxf(z, 0.f) * Wk2[hh];
        }
        float kv = 1.0f / (1.0f + expf(-kp));
        float val = 1.0f + 3.0f * kv;
        if (val < 2.0f) atomicAdd(&g_cnt[0], 1);
        if (val < 3.0f) atomicAdd(&g_cnt[1], 1);
        if (val < 4.0f) atomicAdd(&g_cnt[2], 1);
    }
}

// ---------------------------------------------------------------------------
// sims kernel: sims = x @ patterns^T   (independent of GEMM chain)
// ---------------------------------------------------------------------------
__global__ void sims_kernel(const float* __restrict__ x, const float* __restrict__ pat,
                            float* __restrict__ sims)
{
    __shared__ float xs[64][68];
    __shared__ float ws[64][16];
    int tid = threadIdx.x;
    int row0 = blockIdx.x * 64;
    int e = tid & 15;
    int r0 = (tid >> 4) * 4;
    float acc[4] = {};

    for (int kc = 0; kc < DD; kc += 64) {
#pragma unroll
        for (int it = 0; it < 4; ++it) {
            int idx = tid + it * 256;
            int r = idx >> 4, c4 = idx & 15;
            *(float4*)&xs[r][c4 * 4] =
                *(const float4*)(x + (size_t)(row0 + r) * DD + kc + c4 * 4);
        }
        {
            int pe = tid & 15, k4 = tid >> 4;
            float4 v = *(const float4*)(pat + (size_t)pe * DD + kc + k4 * 4);
            ws[k4 * 4 + 0][pe] = v.x; ws[k4 * 4 + 1][pe] = v.y;
            ws[k4 * 4 + 2][pe] = v.z; ws[k4 * 4 + 3][pe] = v.w;
        }
        __syncthreads();
#pragma unroll 4
        for (int k = 0; k < 64; ++k) {
            float wv = ws[k][e];
            acc[0] += xs[r0 + 0][k] * wv;
            acc[1] += xs[r0 + 1][k] * wv;
            acc[2] += xs[r0 + 2][k] * wv;
            acc[3] += xs[r0 + 3][k] * wv;
        }
        __syncthreads();
    }
#pragma unroll
    for (int j = 0; j < 4; ++j)
        sims[(size_t)(row0 + r0 + j) * EE + e] = acc[j];
}

// ---------------------------------------------------------------------------
// spec2 kernel: spec = sigmoid(sims + h1@Ws2 + bs2); writes bf16 split of
// spec into xT rows [2048, 2064)
// ---------------------------------------------------------------------------
__global__ void spec2_kernel(const float* __restrict__ sims,
                             const float* __restrict__ h1, const float* __restrict__ Ws2,
                             const float* __restrict__ bs2, float* __restrict__ spec,
                             __nv_bfloat16* __restrict__ xth, __nv_bfloat16* __restrict__ xtl)
{
    __shared__ float xs[64][68];
    __shared__ float ws[64][16];
    int tid = threadIdx.x;
    int row0 = blockIdx.x * 64;
    int e = tid & 15;
    int r0 = (tid >> 4) * 4;
    float acc[4];
#pragma unroll
    for (int j = 0; j < 4; ++j)
        acc[j] = sims[(size_t)(row0 + r0 + j) * EE + e];

    for (int kc = 0; kc < HH; kc += 64) {
#pragma unroll
        for (int it = 0; it < 4; ++it) {
            int idx = tid + it * 256;
            int r = idx >> 4, c4 = idx & 15;
            *(float4*)&xs[r][c4 * 4] =
                *(const float4*)(h1 + (size_t)(row0 + r) * HH + kc + c4 * 4);
        }
        {
            int k = tid >> 2, e4 = tid & 3;
            *(float4*)&ws[k][e4 * 4] =
                *(const float4*)(Ws2 + (size_t)(kc + k) * EE + e4 * 4);
        }
        __syncthreads();
#pragma unroll 4
        for (int k = 0; k < 64; ++k) {
            float wv = ws[k][e];
            acc[0] += xs[r0 + 0][k] * wv;
            acc[1] += xs[r0 + 1][k] * wv;
            acc[2] += xs[r0 + 2][k] * wv;
            acc[3] += xs[r0 + 3][k] * wv;
        }
        __syncthreads();
    }
    float b = bs2[e];
#pragma unroll
    for (int j = 0; j < 4; ++j) {
        float vv = acc[j] + b;
        float sg = 1.0f / (1.0f + expf(-vv));
        size_t row = (size_t)(row0 + r0 + j);
        spec[row * EE + e] = sg;
        __nv_bfloat16 h = __float2bfloat16(sg);
        xth[(size_t)(DD + e) * BB + row] = h;
        xtl[(size_t)(DD + e) * BB + row] = __float2bfloat16(sg - __bfloat162float(h));
    }
}

// ---------------------------------------------------------------------------
// probs + topk fused: probs = softmax(h2 @ Wr2 + br2); then top-4 + gates.
// ---------------------------------------------------------------------------
__global__ void probs_topk_kernel(const float* __restrict__ h2, const float* __restrict__ Wr2,
                                  const float* __restrict__ br2, float* __restrict__ probs,
                                  float* __restrict__ gates, float* __restrict__ idxo)
{
    __shared__ float xs[64][68];
    __shared__ float ws[64][16];
    __shared__ float lg[64][17];
    int tid = threadIdx.x;
    int row0 = blockIdx.x * 64;
    int e = tid & 15;
    int r0 = (tid >> 4) * 4;
    float acc[4] = {};

    for (int kc = 0; kc < HH; kc += 64) {
#pragma unroll
        for (int it = 0; it < 4; ++it) {
            int idx = tid + it * 256;
            int r = idx >> 4, c4 = idx & 15;
            *(float4*)&xs[r][c4 * 4] =
                *(const float4*)(h2 + (size_t)(row0 + r) * HH + kc + c4 * 4);
        }
        {
            int k = tid >> 2, e4 = tid & 3;
            *(float4*)&ws[k][e4 * 4] =
                *(const float4*)(Wr2 + (size_t)(kc + k) * EE + e4 * 4);
        }
        __syncthreads();
#pragma unroll 4
        for (int k = 0; k < 64; ++k) {
            float wv = ws[k][e];
            acc[0] += xs[r0 + 0][k] * wv;
            acc[1] += xs[r0 + 1][k] * wv;
            acc[2] += xs[r0 + 2][k] * wv;
            acc[3] += xs[r0 + 3][k] * wv;
        }
        __syncthreads();
    }
    float b = br2[e];
#pragma unroll
    for (int j = 0; j < 4; ++j) lg[r0 + j][e] = acc[j] + b;
    __syncthreads();

    if (tid < 64) {
        int r = tid;
        int row = row0 + r;
        float m = -3.4e38f;
#pragma unroll
        for (int k = 0; k < 16; ++k) m = fmaxf(m, lg[r][k]);
        float pv[16]; float s = 0.f;
#pragma unroll
        for (int k = 0; k < 16; ++k) { pv[k] = expf(lg[r][k] - m); s += pv[k]; }
        float inv = 1.0f / s;
#pragma unroll
        for (int k = 0; k < 16; ++k) pv[k] *= inv;
        float* o = probs + (size_t)row * EE;
#pragma unroll
        for (int k = 0; k < 16; ++k) o[k] = pv[k];

        int c0 = g_cnt[0], c1 = g_cnt[1], c2 = g_cnt[2];
        int kk = (c0 >= 8192) ? 1 : (c1 >= 8192) ? 2 : (c2 >= 8192) ? 3 : 4;

        unsigned used = 0;
        float tv[4]; int ti[4];
#pragma unroll
        for (int s4 = 0; s4 < 4; ++s4) {
            float bv = -1.0f; int bi = 0;
#pragma unroll
            for (int e2 = 0; e2 < 16; ++e2) {
                bool ok = (((used >> e2) & 1u) == 0u) && (pv[e2] > bv);
                if (ok) { bv = pv[e2]; bi = e2; }
            }
            used |= (1u << bi);
            tv[s4] = bv; ti[s4] = bi;
        }
        float gg[4]; float ssum = 0.f;
#pragma unroll
        for (int j = 0; j < 4; ++j) {
            gg[j] = (j < kk) ? expf(tv[j] - tv[0]) : 0.0f;
            ssum += gg[j];
        }
        float ginv = 1.0f / ssum;
#pragma unroll
        for (int j = 0; j < 4; ++j) {
            gates[(size_t)row * 4 + j] = gg[j] * ginv;
            idxo[(size_t)row * 4 + j] = (float)ti[j];
        }
    }
}

// ---------------------------------------------------------------------------
__global__ void init_kernel() { g_cnt[0] = 0; g_cnt[1] = 0; g_cnt[2] = 0; }

// ---------------------------------------------------------------------------
extern "C" void kernel_launch(void* const* d_in, const int* in_sizes, int n_in,
                              void* d_out, int out_size)
{
    const float* x    = (const float*)d_in[0];
    const float* pat  = (const float*)d_in[1];
    const float* Ws1  = (const float*)d_in[2];
    const float* bs1  = (const float*)d_in[3];
    const float* Ws2  = (const float*)d_in[4];
    const float* bs2  = (const float*)d_in[5];
    const float* Wr1  = (const float*)d_in[6];
    const float* br1  = (const float*)d_in[7];
    const float* Wr2  = (const float*)d_in[8];
    const float* br2  = (const float*)d_in[9];
    const float* Wk1  = (const float*)d_in[10];
    const float* bk1  = (const float*)d_in[11];
    const float* Wk2  = (const float*)d_in[12];
    const float* bk2  = (const float*)d_in[13];

    float* out = (float*)d_out;
    float* o_gates = out;                      // 16384*4
    float* o_idx   = out + 65536;              // 16384*4
    float* o_probs = out + 131072;             // 16384*16
    float* o_stats = out + 393216;             // 16384*6

    void* p;
    cudaGetSymbolAddress(&p, g_h1);   float* h1 = (float*)p;
    cudaGetSymbolAddress(&p, g_h2);   float* h2 = (float*)p;
    cudaGetSymbolAddress(&p, g_spec); float* spec = (float*)p;
    cudaGetSymbolAddress(&p, g_sims); float* sims = (float*)p;
    cudaGetSymbolAddress(&p, g_xth);  __nv_bfloat16* xth = (__nv_bfloat16*)p;
    cudaGetSymbolAddress(&p, g_xtl);  __nv_bfloat16* xtl = (__nv_bfloat16*)p;
    cudaGetSymbolAddress(&p, g_w1h);  __nv_bfloat16* w1h = (__nv_bfloat16*)p;
    cudaGetSymbolAddress(&p, g_w1l);  __nv_bfloat16* w1l = (__nv_bfloat16*)p;
    cudaGetSymbolAddress(&p, g_w2h);  __nv_bfloat16* w2h = (__nv_bfloat16*)p;
    cudaGetSymbolAddress(&p, g_w2l);  __nv_bfloat16* w2l = (__nv_bfloat16*)p;

    cudaFuncSetAttribute(gemm_mma, cudaFuncAttributeMaxDynamicSharedMemorySize, GEMM_SMEM);

    // side stream + fork/join events (created once; identical topology per call)
    static cudaStream_t s1 = 0;
    static cudaEvent_t evF = 0, evW = 0, evA = 0, evB = 0;
    if (evB == 0) {
        cudaStreamCreateWithFlags(&s1, cudaStreamNonBlocking);
        cudaEventCreateWithFlags(&evF, cudaEventDisableTiming);
        cudaEventCreateWithFlags(&evW, cudaEventDisableTiming);
        cudaEventCreateWithFlags(&evA, cudaEventDisableTiming);
        cudaEventCreateWithFlags(&evB, cudaEventDisableTiming);
    }

    // fork s1 from the main (default) stream
    cudaEventRecord(evF, 0);
    cudaStreamWaitEvent(s1, evF, 0);

    // ---- s1: independent work (overlapped with split_xT / GEMM1) ----
    split_w_kernel<<<(KTOT * HH) / 256, 256, 0, s1>>>(Ws1, DD, w1h, w1l);
    cudaEventRecord(evW, s1);                    // w1 ready
    init_kernel<<<1, 1, 0, s1>>>();
    split_w_kernel<<<(KTOT * HH) / 256, 256, 0, s1>>>(Wr1, DD + EE, w2h, w2l);
    sims_kernel<<<BB / 64, 256, 0, s1>>>(x, pat, sims);
    cudaEventRecord(evA, s1);                    // sims + w2 ready
    stats_kernel<<<BB, 256, 0, s1>>>(x, o_stats, Wk1, bk1, Wk2, bk2);
    cudaEventRecord(evB, s1);                    // stats/g_cnt ready

    // ---- s0 (default stream): GEMM chain ----
    {
        dim3 tg(KTOT / 32, BB / 64);
        split_xT_kernel<<<tg, 256>>>(x, xth, xtl);
    }

    dim3 gg(HH / 128, BB / 128);
    cudaStreamWaitEvent(0, evW, 0);              // need w1h/w1l
    gemm_mma<<<gg, 256, GEMM_SMEM>>>(xth, xtl, w1h, w1l, bs1, h1, 64);

    cudaStreamWaitEvent(0, evA, 0);              // need sims + w2h/w2l
    spec2_kernel<<<BB / 64, 256>>>(sims, h1, Ws2, bs2, spec, xth, xtl);

    gemm_mma<<<gg, 256, GEMM_SMEM>>>(xth, xtl, w2h, w2l, br1, h2, 65);

    cudaStreamWaitEvent(0, evB, 0);              // need g_cnt
    probs_topk_kernel<<<BB / 64, 256>>>(h2, Wr2, br2, o_probs, o_gates, o_idx);

    (void)in_sizes; (void)n_in; (void)out_size;
}

// round 11
// speedup vs baseline: 1.0909x; 1.0849x over previous
#include <cuda_runtime.h>
#include <cuda_bf16.h>
#include <cstdint>

// Problem constants (fixed shapes)
#define BB 16384
#define DD 2048
#define HH 1024
#define EE 16
#define TOPC 409
#define KTOT 2080          // padded K: 2048 + 16 (spec) + 16 pad, %32==0

// ---------------------------------------------------------------------------
// Device global scratch (no runtime allocation allowed)
// ---------------------------------------------------------------------------
__device__ float g_h1[(size_t)BB * HH];
__device__ float g_h2[(size_t)BB * HH];
__device__ float g_spec[(size_t)BB * EE];
__device__ float g_sims[(size_t)BB * EE];
__device__ __nv_bfloat16 g_xth[(size_t)KTOT * BB];   // x^T hi, k-major [K][B]
__device__ __nv_bfloat16 g_xtl[(size_t)KTOT * BB];   // x^T lo
__device__ __nv_bfloat16 g_w1h[(size_t)KTOT * HH];
__device__ __nv_bfloat16 g_w1l[(size_t)KTOT * HH];
__device__ __nv_bfloat16 g_w2h[(size_t)KTOT * HH];
__device__ __nv_bfloat16 g_w2l[(size_t)KTOT * HH];
__device__ int g_cnt[3];

// ---------------------------------------------------------------------------
// helpers
// ---------------------------------------------------------------------------
__device__ __forceinline__ uint32_t smem_u32(const void* p) {
    uint32_t a;
    asm("{ .reg .u64 t; cvta.to.shared.u64 t, %1; cvt.u32.u64 %0, t; }" : "=r"(a) : "l"(p));
    return a;
}

#define CPA16(dst, src) \
    asm volatile("cp.async.cg.shared.global [%0], [%1], 16;" :: "r"(dst), "l"(src))
#define CPA_COMMIT() asm volatile("cp.async.commit_group;" ::: "memory")

#define LDSM4T(r0, r1, r2, r3, addr) \
    asm volatile("ldmatrix.sync.aligned.m8n8.x4.trans.shared.b16 {%0,%1,%2,%3}, [%4];" \
                 : "=r"(r0), "=r"(r1), "=r"(r2), "=r"(r3) : "r"(addr) : "memory")

#define MMA16816(d, a, b0, b1) \
    asm volatile("mma.sync.aligned.m16n8k16.row.col.f32.bf16.bf16.f32 " \
                 "{%0,%1,%2,%3}, {%4,%5,%6,%7}, {%8,%9}, {%0,%1,%2,%3};" \
                 : "+f"((d)[0]), "+f"((d)[1]), "+f"((d)[2]), "+f"((d)[3]) \
                 : "r"((a)[0]), "r"((a)[1]), "r"((a)[2]), "r"((a)[3]), \
                   "r"(b0), "r"(b1))

// ---------------------------------------------------------------------------
// split + transpose x: [B, D] fp32 -> xT hi/lo bf16 [KTOT][B]; zero k>=2048.
// ---------------------------------------------------------------------------
__global__ void split_xT_kernel(const float* __restrict__ x,
                                __nv_bfloat16* __restrict__ xh,
                                __nv_bfloat16* __restrict__ xl)
{
    __shared__ float t[64][33];
    int k0 = blockIdx.x * 32;        // 65 tiles
    int m0 = blockIdx.y * 64;        // 256 tiles
    int tid = threadIdx.x;

    int k = tid >> 3;                // 0..31
    int mm = (tid & 7) * 8;          // 0..56

    if (k0 < DD) {
        int r = tid >> 2;            // 0..63
        int c = (tid & 3) * 8;       // 0,8,16,24
        const float* src = x + (size_t)(m0 + r) * DD + k0 + c;
        float4 v0 = *(const float4*)src;
        float4 v1 = *(const float4*)(src + 4);
        t[r][c + 0] = v0.x; t[r][c + 1] = v0.y; t[r][c + 2] = v0.z; t[r][c + 3] = v0.w;
        t[r][c + 4] = v1.x; t[r][c + 5] = v1.y; t[r][c + 6] = v1.z; t[r][c + 7] = v1.w;
        __syncthreads();

        __nv_bfloat16 h8[8], l8[8];
#pragma unroll
        for (int j = 0; j < 8; ++j) {
            float v = t[mm + j][k];
            __nv_bfloat16 h = __float2bfloat16(v);
            h8[j] = h;
            l8[j] = __float2bfloat16(v - __bfloat162float(h));
        }
        *(uint4*)(xh + (size_t)(k0 + k) * BB + m0 + mm) = *(uint4*)h8;
        *(uint4*)(xl + (size_t)(k0 + k) * BB + m0 + mm) = *(uint4*)l8;
    } else {
        uint4 z = {0, 0, 0, 0};
        *(uint4*)(xh + (size_t)(k0 + k) * BB + m0 + mm) = z;
        *(uint4*)(xl + (size_t)(k0 + k) * BB + m0 + mm) = z;
    }
}

// ---------------------------------------------------------------------------
// split W: [Klim, 1024] fp32 -> hi/lo bf16 [KTOT][1024], zero past Klim
// ---------------------------------------------------------------------------
__global__ void split_w_kernel(const float* __restrict__ W, int Klim,
                               __nv_bfloat16* __restrict__ wh,
                               __nv_bfloat16* __restrict__ wl)
{
    int idx = blockIdx.x * 256 + threadIdx.x;   // over KTOT*1024
    int k = idx >> 10, n = idx & 1023;
    float v = (k < Klim) ? W[(size_t)k * HH + n] : 0.0f;
    __nv_bfloat16 h = __float2bfloat16(v);
    wh[idx] = h;
    wl[idx] = __float2bfloat16(v - __bfloat162float(h));
}

// ---------------------------------------------------------------------------
// HMMA split-bf16 GEMM (round-4 proven version): BK=32, 2-stage cp.async.
// CTA tile 128x128, 8 warps (2m x 4n), each warp 64x32. 2 CTAs/SM.
// ---------------------------------------------------------------------------
#define STG_BYTES 32768
#define GEMM_SMEM (2 * STG_BYTES + 1024)

__device__ __forceinline__ void gemm_ld_stage(
    uint32_t db, int s, int c,
    const __nv_bfloat16* __restrict__ Ah, const __nv_bfloat16* __restrict__ Al,
    const __nv_bfloat16* __restrict__ Wh, const __nv_bfloat16* __restrict__ Wl,
    int m0, int n0, int tid)
{
    int k  = tid >> 3;                 // 0..31
    int mc = (tid & 7) * 2;            // chunk pair
    uint32_t base = db + s * STG_BYTES;
    uint32_t d0 = k * 256 + ((mc ^ (k & 7)) << 4);
    uint32_t d1 = k * 256 + (((mc + 1) ^ (k & 7)) << 4);
    size_t ka = (size_t)(c * 32 + k);
    const char* pah = (const char*)(Ah + ka * BB + m0 + mc * 8);
    const char* pal = (const char*)(Al + ka * BB + m0 + mc * 8);
    const char* pwh = (const char*)(Wh + ka * HH + n0 + mc * 8);
    const char* pwl = (const char*)(Wl + ka * HH + n0 + mc * 8);
    CPA16(base + d0,         pah);      CPA16(base + d1,         pah + 16);
    CPA16(base + 8192  + d0, pal);      CPA16(base + 8192  + d1, pal + 16);
    CPA16(base + 16384 + d0, pwh);      CPA16(base + 16384 + d1, pwh + 16);
    CPA16(base + 24576 + d0, pwl);      CPA16(base + 24576 + d1, pwl + 16);
    CPA_COMMIT();
}

__global__ __launch_bounds__(256, 1)
void gemm_mma(const __nv_bfloat16* __restrict__ Ah, const __nv_bfloat16* __restrict__ Al,
              const __nv_bfloat16* __restrict__ Wh, const __nv_bfloat16* __restrict__ Wl,
              const float* __restrict__ bias, float* __restrict__ C, int nch)
{
    extern __shared__ char smem[];
    uint32_t db = (smem_u32(smem) + 1023) & ~1023u;
    int tid = threadIdx.x, lane = tid & 31, wid = tid >> 5;
    int wm = wid >> 2, wn = wid & 3;
    int m0 = blockIdx.y * 128, n0 = blockIdx.x * 128;

    int q = lane >> 3, r = lane & 7;
    int kq = ((q >> 1) << 3) + r;       // 0..15
    int sw = kq & 7;
    uint32_t offA[4], offB[2];
#pragma unroll
    for (int mt = 0; mt < 4; ++mt) {
        int cc = wm * 8 + mt * 2 + (q & 1);
        offA[mt] = kq * 256 + ((cc ^ sw) << 4);
    }
#pragma unroll
    for (int bt = 0; bt < 2; ++bt) {
        int cc = wn * 4 + bt * 2 + (q & 1);
        offB[bt] = kq * 256 + ((cc ^ sw) << 4);
    }

    float acc[4][4][4] = {};

    gemm_ld_stage(db, 0, 0, Ah, Al, Wh, Wl, m0, n0, tid);

    for (int c = 0; c < nch; ++c) {
        if (c + 1 < nch) {
            gemm_ld_stage(db, (c + 1) & 1, c + 1, Ah, Al, Wh, Wl, m0, n0, tid);
            asm volatile("cp.async.wait_group 1;" ::: "memory");
        } else {
            asm volatile("cp.async.wait_group 0;" ::: "memory");
        }
        __syncthreads();

        uint32_t sbase = db + (c & 1) * STG_BYTES;
#pragma unroll
        for (int ks = 0; ks < 2; ++ks) {
            uint32_t sb = sbase + ks * 4096;
            uint32_t ah[4][4], al_[4][4], bh_[2][4], bl_[2][4];
#pragma unroll
            for (int mt = 0; mt < 4; ++mt) {
                LDSM4T(ah[mt][0],  ah[mt][1],  ah[mt][2],  ah[mt][3],  sb + offA[mt]);
                LDSM4T(al_[mt][0], al_[mt][1], al_[mt][2], al_[mt][3], sb + 8192 + offA[mt]);
            }
#pragma unroll
            for (int bt = 0; bt < 2; ++bt) {
                LDSM4T(bh_[bt][0], bh_[bt][1], bh_[bt][2], bh_[bt][3], sb + 16384 + offB[bt]);
                LDSM4T(bl_[bt][0], bl_[bt][1], bl_[bt][2], bl_[bt][3], sb + 24576 + offB[bt]);
            }
#pragma unroll
            for (int mt = 0; mt < 4; ++mt)
#pragma unroll
                for (int nt = 0; nt < 4; ++nt) {
                    int bt = nt >> 1, p = nt & 1;
                    MMA16816(acc[mt][nt], ah[mt], bh_[bt][p], bh_[bt][p + 2]);
                }
#pragma unroll
            for (int mt = 0; mt < 4; ++mt)
#pragma unroll
                for (int nt = 0; nt < 4; ++nt) {
                    int bt = nt >> 1, p = nt & 1;
                    MMA16816(acc[mt][nt], ah[mt], bl_[bt][p], bl_[bt][p + 2]);
                }
#pragma unroll
            for (int mt = 0; mt < 4; ++mt)
#pragma unroll
                for (int nt = 0; nt < 4; ++nt) {
                    int bt = nt >> 1, p = nt & 1;
                    MMA16816(acc[mt][nt], al_[mt], bh_[bt][p], bh_[bt][p + 2]);
                }
        }
        __syncthreads();
    }

    int g = lane >> 2, t2 = (lane & 3) * 2;
#pragma unroll
    for (int nt = 0; nt < 4; ++nt) {
        int col = n0 + wn * 32 + nt * 8 + t2;
        float2 bv = *(const float2*)(bias + col);
#pragma unroll
        for (int mt = 0; mt < 4; ++mt) {
            int row = m0 + wm * 64 + mt * 16 + g;
            float2 o0, o1;
            o0.x = fmaxf(acc[mt][nt][0] + bv.x, 0.f);
            o0.y = fmaxf(acc[mt][nt][1] + bv.y, 0.f);
            o1.x = fmaxf(acc[mt][nt][2] + bv.x, 0.f);
            o1.y = fmaxf(acc[mt][nt][3] + bv.y, 0.f);
            *(float2*)(C + (size_t)row * HH + col) = o0;
            *(float2*)(C + (size_t)(row + 8) * HH + col) = o1;
        }
    }
}

// ---------------------------------------------------------------------------
// Stats kernel: register-resident; moments + top-409 |x| sum via 2-pass radix
// (16 prefix bits + threshold correction). Fused k-predictor.
// ---------------------------------------------------------------------------
__global__ void stats_kernel(const float* __restrict__ x, float* __restrict__ stats,
                             const float* __restrict__ Wk1, const float* __restrict__ bk1,
                             const float* __restrict__ Wk2, const float* __restrict__ bk2)
{
    __shared__ float red[48];
    __shared__ float sres[8];
    __shared__ int hist[256];
    __shared__ int warptot[8];
    __shared__ unsigned s_pref;
    __shared__ int s_need;

    int row = blockIdx.x;
    int tid = threadIdx.x;
    int lane = tid & 31, w = tid >> 5;

    const float4* xr = (const float4*)(x + (size_t)row * DD);
    float4 a4 = xr[tid * 2], b4 = xr[tid * 2 + 1];
    float v[8] = {a4.x, a4.y, a4.z, a4.w, b4.x, b4.y, b4.z, b4.w};
    unsigned bb[8];
#pragma unroll
    for (int j = 0; j < 8; ++j) bb[j] = __float_as_uint(v[j]) & 0x7fffffffu;

    float sum = 0.f, sumsq = 0.f, suma = 0.f, zc = 0.f, maxa = 0.f;
#pragma unroll
    for (int j = 0; j < 8; ++j) {
        float vv = v[j];
        sum += vv; sumsq += vv * vv;
        float ab = fabsf(vv);
        suma += ab; maxa = fmaxf(maxa, ab);
        zc += (vv == 0.0f) ? 1.f : 0.f;
    }
#pragma unroll
    for (int o = 16; o; o >>= 1) {
        sum   += __shfl_down_sync(0xffffffffu, sum,   o);
        sumsq += __shfl_down_sync(0xffffffffu, sumsq, o);
        suma  += __shfl_down_sync(0xffffffffu, suma,  o);
        zc    += __shfl_down_sync(0xffffffffu, zc,    o);
        maxa   = fmaxf(maxa, __shfl_down_sync(0xffffffffu, maxa, o));
    }
    if (lane == 0) {
        red[w * 5 + 0] = sum;  red[w * 5 + 1] = sumsq; red[w * 5 + 2] = suma;
        red[w * 5 + 3] = zc;   red[w * 5 + 4] = maxa;
    }
    __syncthreads();
    if (tid < 5) {
        float r0 = red[tid];
        if (tid < 4) { for (int w2 = 1; w2 < 8; ++w2) r0 += red[w2 * 5 + tid]; }
        else         { for (int w2 = 1; w2 < 8; ++w2) r0 = fmaxf(r0, red[w2 * 5 + tid]); }
        sres[tid] = r0;
    }
    __syncthreads();
    sum = sres[0]; sumsq = sres[1]; suma = sres[2]; zc = sres[3]; maxa = sres[4];
    float mean = sum * (1.0f / 2048.0f);

    float s2 = 0.f, s3 = 0.f;
#pragma unroll
    for (int j = 0; j < 8; ++j) {
        float d = v[j] - mean;
        s2 += d * d;
        s3 += d * d * d;
    }
#pragma unroll
    for (int o = 16; o; o >>= 1) {
        s2 += __shfl_down_sync(0xffffffffu, s2, o);
        s3 += __shfl_down_sync(0xffffffffu, s3, o);
    }
    __syncthreads();
    if (lane == 0) { red[w * 2 + 0] = s2; red[w * 2 + 1] = s3; }
    __syncthreads();
    if (tid < 2) {
        float r0 = red[tid];
        for (int w2 = 1; w2 < 8; ++w2) r0 += red[w2 * 2 + tid];
        sres[5 + tid] = r0;
    }
    __syncthreads();
    s2 = sres[5]; s3 = sres[6];
    float var  = s2 * (1.0f / 2047.0f);
    float stdv = sqrtf(var + 1e-8f);
    float skew = (s3 * (1.0f / 2048.0f)) / (stdv * stdv * stdv);

    unsigned prefix = 0;
    int need = TOPC;
#pragma unroll
    for (int pass = 0; pass < 2; ++pass) {
        int shift = (pass == 0) ? 23 : 15;
        hist[tid] = 0;
        __syncthreads();
#pragma unroll
        for (int j = 0; j < 8; ++j) {
            bool match = (pass == 0) || ((bb[j] >> 23) == prefix);
            unsigned bin = (bb[j] >> shift) & 255;
            unsigned key = match ? bin : 0xffffffffu;
            unsigned grp = __match_any_sync(0xffffffffu, key);
            int leader = __ffs(grp) - 1;
            if (match && lane == leader)
                atomicAdd(&hist[bin], __popc(grp));
        }
        __syncthreads();
        int h = hist[tid];
        int suf = h;
#pragma unroll
        for (int o = 1; o < 32; o <<= 1) {
            int t = __shfl_down_sync(0xffffffffu, suf, o);
            if (lane + o < 32) suf += t;
        }
        if (lane == 0) warptot[w] = suf;
        __syncthreads();
        int tail = 0;
#pragma unroll
        for (int w2 = 0; w2 < 8; ++w2)
            if (w2 > w) tail += warptot[w2];
        int incl = suf + tail;
        int excl = incl - h;
        if (excl < need && need <= incl) {
            s_pref = (prefix << 8) | (unsigned)tid;
            s_need = need - excl;
        }
        __syncthreads();
        prefix = s_pref;
        need = s_need;
        __syncthreads();
    }

    unsigned tb = prefix << 15;
    float tsum = 0.f;
    int tcnt = 0;
#pragma unroll
    for (int j = 0; j < 8; ++j)
        if (bb[j] >= tb) { tsum += __uint_as_float(bb[j]); tcnt++; }
#pragma unroll
    for (int o = 16; o; o >>= 1) {
        tsum += __shfl_down_sync(0xffffffffu, tsum, o);
        tcnt += __shfl_down_sync(0xffffffffu, tcnt, o);
    }
    if (lane == 0) { red[w] = tsum; warptot[w] = tcnt; }
    __syncthreads();
    if (tid == 0) {
        float tt = 0.f; int nc = 0;
        for (int w2 = 0; w2 < 8; ++w2) { tt += red[w2]; nc += warptot[w2]; }
        float tmid = __uint_as_float(tb + (1u << 14));
        tt -= (float)(nc - TOPC) * tmid;
        float st[6];
        st[0] = zc * (1.0f / 2048.0f);
        st[1] = var;
        st[2] = maxa;
        st[3] = sqrtf(sumsq);
        st[4] = skew;
        st[5] = tt / (suma + 1e-8f);
        float* o = stats + (size_t)row * 6;
#pragma unroll
        for (int i = 0; i < 6; ++i) o[i] = st[i];

        float kp = bk2[0];
#pragma unroll
        for (int hh = 0; hh < 16; ++hh) {
            float z = bk1[hh];
#pragma unroll
            for (int i = 0; i < 6; ++i) z += st[i] * Wk1[i * 16 + hh];
            kp += fmaxf(z, 0.f) * Wk2[hh];
        }
        float kv = 1.0f / (1.0f + expf(-kp));
        float val = 1.0f + 3.0f * kv;
        if (val < 2.0f) atomicAdd(&g_cnt[0], 1);
        if (val < 3.0f) atomicAdd(&g_cnt[1], 1);
        if (val < 4.0f) atomicAdd(&g_cnt[2], 1);
    }
}

// ---------------------------------------------------------------------------
// sims kernel: sims = x @ patterns^T   (independent of GEMM chain)
// ---------------------------------------------------------------------------
__global__ void sims_kernel(const float* __restrict__ x, const float* __restrict__ pat,
                            float* __restrict__ sims)
{
    __shared__ float xs[64][68];
    __shared__ float ws[64][16];
    int tid = threadIdx.x;
    int row0 = blockIdx.x * 64;
    int e = tid & 15;
    int r0 = (tid >> 4) * 4;
    float acc[4] = {};

    for (int kc = 0; kc < DD; kc += 64) {
#pragma unroll
        for (int it = 0; it < 4; ++it) {
            int idx = tid + it * 256;
            int r = idx >> 4, c4 = idx & 15;
            *(float4*)&xs[r][c4 * 4] =
                *(const float4*)(x + (size_t)(row0 + r) * DD + kc + c4 * 4);
        }
        {
            int pe = tid & 15, k4 = tid >> 4;
            float4 v = *(const float4*)(pat + (size_t)pe * DD + kc + k4 * 4);
            ws[k4 * 4 + 0][pe] = v.x; ws[k4 * 4 + 1][pe] = v.y;
            ws[k4 * 4 + 2][pe] = v.z; ws[k4 * 4 + 3][pe] = v.w;
        }
        __syncthreads();
#pragma unroll 4
        for (int k = 0; k < 64; ++k) {
            float wv = ws[k][e];
            acc[0] += xs[r0 + 0][k] * wv;
            acc[1] += xs[r0 + 1][k] * wv;
            acc[2] += xs[r0 + 2][k] * wv;
            acc[3] += xs[r0 + 3][k] * wv;
        }
        __syncthreads();
    }
#pragma unroll
    for (int j = 0; j < 4; ++j)
        sims[(size_t)(row0 + r0 + j) * EE + e] = acc[j];
}

// ---------------------------------------------------------------------------
// spec2 kernel: spec = sigmoid(sims + h1@Ws2 + bs2); writes bf16 split of
// spec into xT rows [2048, 2064)
// ---------------------------------------------------------------------------
__global__ void spec2_kernel(const float* __restrict__ sims,
                             const float* __restrict__ h1, const float* __restrict__ Ws2,
                             const float* __restrict__ bs2, float* __restrict__ spec,
                             __nv_bfloat16* __restrict__ xth, __nv_bfloat16* __restrict__ xtl)
{
    __shared__ float xs[64][68];
    __shared__ float ws[64][16];
    int tid = threadIdx.x;
    int row0 = blockIdx.x * 64;
    int e = tid & 15;
    int r0 = (tid >> 4) * 4;
    float acc[4];
#pragma unroll
    for (int j = 0; j < 4; ++j)
        acc[j] = sims[(size_t)(row0 + r0 + j) * EE + e];

    for (int kc = 0; kc < HH; kc += 64) {
#pragma unroll
        for (int it = 0; it < 4; ++it) {
            int idx = tid + it * 256;
            int r = idx >> 4, c4 = idx & 15;
            *(float4*)&xs[r][c4 * 4] =
                *(const float4*)(h1 + (size_t)(row0 + r) * HH + kc + c4 * 4);
        }
        {
            int k = tid >> 2, e4 = tid & 3;
            *(float4*)&ws[k][e4 * 4] =
                *(const float4*)(Ws2 + (size_t)(kc + k) * EE + e4 * 4);
        }
        __syncthreads();
#pragma unroll 4
        for (int k = 0; k < 64; ++k) {
            float wv = ws[k][e];
            acc[0] += xs[r0 + 0][k] * wv;
            acc[1] += xs[r0 + 1][k] * wv;
            acc[2] += xs[r0 + 2][k] * wv;
            acc[3] += xs[r0 + 3][k] * wv;
        }
        __syncthreads();
    }
    float b = bs2[e];
#pragma unroll
    for (int j = 0; j < 4; ++j) {
        float vv = acc[j] + b;
        float sg = 1.0f / (1.0f + expf(-vv));
        size_t row = (size_t)(row0 + r0 + j);
        spec[row * EE + e] = sg;
        __nv_bfloat16 h = __float2bfloat16(sg);
        xth[(size_t)(DD + e) * BB + row] = h;
        xtl[(size_t)(DD + e) * BB + row] = __float2bfloat16(sg - __bfloat162float(h));
    }
}

// ---------------------------------------------------------------------------
// probs kernel: probs = softmax(h2 @ Wr2 + br2)
// ---------------------------------------------------------------------------
__global__ void probs_kernel(const float* __restrict__ h2, const float* __restrict__ Wr2,
                             const float* __restrict__ br2, float* __restrict__ probs)
{
    __shared__ float xs[64][68];
    __shared__ float ws[64][16];
    __shared__ float lg[64][17];
    int tid = threadIdx.x;
    int row0 = blockIdx.x * 64;
    int e = tid & 15;
    int r0 = (tid >> 4) * 4;
    float acc[4] = {};

    for (int kc = 0; kc < HH; kc += 64) {
#pragma unroll
        for (int it = 0; it < 4; ++it) {
            int idx = tid + it * 256;
            int r = idx >> 4, c4 = idx & 15;
            *(float4*)&xs[r][c4 * 4] =
                *(const float4*)(h2 + (size_t)(row0 + r) * HH + kc + c4 * 4);
        }
        {
            int k = tid >> 2, e4 = tid & 3;
            *(float4*)&ws[k][e4 * 4] =
                *(const float4*)(Wr2 + (size_t)(kc + k) * EE + e4 * 4);
        }
        __syncthreads();
#pragma unroll 4
        for (int k = 0; k < 64; ++k) {
            float wv = ws[k][e];
            acc[0] += xs[r0 + 0][k] * wv;
            acc[1] += xs[r0 + 1][k] * wv;
            acc[2] += xs[r0 + 2][k] * wv;
            acc[3] += xs[r0 + 3][k] * wv;
        }
        __syncthreads();
    }
    float b = br2[e];
#pragma unroll
    for (int j = 0; j < 4; ++j) lg[r0 + j][e] = acc[j] + b;
    __syncthreads();

    if (tid < 64) {
        int r = tid;
        float m = -3.4e38f;
#pragma unroll
        for (int k = 0; k < 16; ++k) m = fmaxf(m, lg[r][k]);
        float pv[16]; float s = 0.f;
#pragma unroll
        for (int k = 0; k < 16; ++k) { pv[k] = expf(lg[r][k] - m); s += pv[k]; }
        float inv = 1.0f / s;
        float* o = probs + (size_t)(row0 + r) * EE;
#pragma unroll
        for (int k = 0; k < 16; ++k) o[k] = pv[k] * inv;
    }
}

// ---------------------------------------------------------------------------
// top-k + gates (k derived per-thread from g_cnt counts; median = 8192nd)
// ---------------------------------------------------------------------------
__global__ void topk_kernel(const float* __restrict__ probs,
                            float* __restrict__ gates, float* __restrict__ idxo)
{
    int row = blockIdx.x * 256 + threadIdx.x;
    int c0 = g_cnt[0], c1 = g_cnt[1], c2 = g_cnt[2];
    int k = (c0 >= 8192) ? 1 : (c1 >= 8192) ? 2 : (c2 >= 8192) ? 3 : 4;

    float p[16];
    const float4* pr = (const float4*)(probs + (size_t)row * EE);
    ((float4*)p)[0] = pr[0]; ((float4*)p)[1] = pr[1];
    ((float4*)p)[2] = pr[2]; ((float4*)p)[3] = pr[3];

    unsigned used = 0;
    float tv[4]; int ti[4];
#pragma unroll
    for (int s = 0; s < 4; ++s) {
        float bv = -1.0f; int bi = 0;
#pragma unroll
        for (int e = 0; e < 16; ++e) {
            bool ok = (((used >> e) & 1u) == 0u) && (p[e] > bv);
            if (ok) { bv = p[e]; bi = e; }
        }
        used |= (1u << bi);
        tv[s] = bv; ti[s] = bi;
    }
    float g[4]; float ssum = 0.f;
#pragma unroll
    for (int j = 0; j < 4; ++j) {
        g[j] = (j < k) ? expf(tv[j] - tv[0]) : 0.0f;
        ssum += g[j];
    }
    float inv = 1.0f / ssum;
#pragma unroll
    for (int j = 0; j < 4; ++j) {
        gates[(size_t)row * 4 + j] = g[j] * inv;
        idxo[(size_t)row * 4 + j] = (float)ti[j];
    }
}

// ---------------------------------------------------------------------------
__global__ void init_kernel() { g_cnt[0] = 0; g_cnt[1] = 0; g_cnt[2] = 0; }

// ---------------------------------------------------------------------------
extern "C" void kernel_launch(void* const* d_in, const int* in_sizes, int n_in,
                              void* d_out, int out_size)
{
    const float* x    = (const float*)d_in[0];
    const float* pat  = (const float*)d_in[1];
    const float* Ws1  = (const float*)d_in[2];
    const float* bs1  = (const float*)d_in[3];
    const float* Ws2  = (const float*)d_in[4];
    const float* bs2  = (const float*)d_in[5];
    const float* Wr1  = (const float*)d_in[6];
    const float* br1  = (const float*)d_in[7];
    const float* Wr2  = (const float*)d_in[8];
    const float* br2  = (const float*)d_in[9];
    const float* Wk1  = (const float*)d_in[10];
    const float* bk1  = (const float*)d_in[11];
    const float* Wk2  = (const float*)d_in[12];
    const float* bk2  = (const float*)d_in[13];

    float* out = (float*)d_out;
    float* o_gates = out;                      // 16384*4
    float* o_idx   = out + 65536;              // 16384*4
    float* o_probs = out + 131072;             // 16384*16
    float* o_stats = out + 393216;             // 16384*6

    void* p;
    cudaGetSymbolAddress(&p, g_h1);   float* h1 = (float*)p;
    cudaGetSymbolAddress(&p, g_h2);   float* h2 = (float*)p;
    cudaGetSymbolAddress(&p, g_spec); float* spec = (float*)p;
    cudaGetSymbolAddress(&p, g_sims); float* sims = (float*)p;
    cudaGetSymbolAddress(&p, g_xth);  __nv_bfloat16* xth = (__nv_bfloat16*)p;
    cudaGetSymbolAddress(&p, g_xtl);  __nv_bfloat16* xtl = (__nv_bfloat16*)p;
    cudaGetSymbolAddress(&p, g_w1h);  __nv_bfloat16* w1h = (__nv_bfloat16*)p;
    cudaGetSymbolAddress(&p, g_w1l);  __nv_bfloat16* w1l = (__nv_bfloat16*)p;
    cudaGetSymbolAddress(&p, g_w2h);  __nv_bfloat16* w2h = (__nv_bfloat16*)p;
    cudaGetSymbolAddress(&p, g_w2l);  __nv_bfloat16* w2l = (__nv_bfloat16*)p;

    cudaFuncSetAttribute(gemm_mma, cudaFuncAttributeMaxDynamicSharedMemorySize, GEMM_SMEM);

    // side stream + fork/join events (created once; identical topology per call)
    static cudaStream_t s1 = 0;
    static cudaEvent_t evF = 0, evA = 0, evB = 0;
    if (evB == 0) {
        cudaStreamCreateWithFlags(&s1, cudaStreamNonBlocking);
        cudaEventCreateWithFlags(&evF, cudaEventDisableTiming);
        cudaEventCreateWithFlags(&evA, cudaEventDisableTiming);
        cudaEventCreateWithFlags(&evB, cudaEventDisableTiming);
    }

    // fork s1 from the main (default) stream
    cudaEventRecord(evF, 0);
    cudaStreamWaitEvent(s1, evF, 0);

    // ---- s1: independent work (hidden under GEMM1) ----
    init_kernel<<<1, 1, 0, s1>>>();
    split_w_kernel<<<(KTOT * HH) / 256, 256, 0, s1>>>(Wr1, DD + EE, w2h, w2l);
    sims_kernel<<<BB / 64, 256, 0, s1>>>(x, pat, sims);
    cudaEventRecord(evA, s1);                    // sims + w2 ready
    stats_kernel<<<BB, 256, 0, s1>>>(x, o_stats, Wk1, bk1, Wk2, bk2);
    cudaEventRecord(evB, s1);                    // stats/g_cnt ready

    // ---- s0 (default stream): GEMM chain ----
    {
        dim3 tg(KTOT / 32, BB / 64);
        split_xT_kernel<<<tg, 256>>>(x, xth, xtl);
    }
    split_w_kernel<<<(KTOT * HH) / 256, 256>>>(Ws1, DD, w1h, w1l);

    dim3 gg(HH / 128, BB / 128);
    gemm_mma<<<gg, 256, GEMM_SMEM>>>(xth, xtl, w1h, w1l, bs1, h1, 64);

    cudaStreamWaitEvent(0, evA, 0);              // need sims + w2h/w2l
    spec2_kernel<<<BB / 64, 256>>>(sims, h1, Ws2, bs2, spec, xth, xtl);

    gemm_mma<<<gg, 256, GEMM_SMEM>>>(xth, xtl, w2h, w2l, br1, h2, 65);

    probs_kernel<<<BB / 64, 256>>>(h2, Wr2, br2, o_probs);

    cudaStreamWaitEvent(0, evB, 0);              // need g_cnt
    topk_kernel<<<BB / 256, 256>>>(o_probs, o_gates, o_idx);

    (void)in_sizes; (void)n_in; (void)out_size;
}

// round 12
// speedup vs baseline: 1.1163x; 1.0233x over previous
#include <cuda_runtime.h>
#include <cuda_bf16.h>
#include <cstdint>

// Problem constants (fixed shapes)
#define BB 16384
#define DD 2048
#define HH 1024
#define EE 16
#define TOPC 409
#define KTOT 2048          // split arrays cover exactly K=2048 now (rank-16 tail handled in fp32)

// ---------------------------------------------------------------------------
// Device global scratch (no runtime allocation allowed)
// ---------------------------------------------------------------------------
__device__ float g_h1[(size_t)BB * HH];
__device__ float g_h2[(size_t)BB * HH];      // h2raw: x@Wr1main + br1 (pre-relu)
__device__ float g_spec[(size_t)BB * EE];
__device__ float g_sims[(size_t)BB * EE];
__device__ __nv_bfloat16 g_xth[(size_t)KTOT * BB];   // x^T hi, k-major [K][B]
__device__ __nv_bfloat16 g_xtl[(size_t)KTOT * BB];   // x^T lo
__device__ __nv_bfloat16 g_w1h[(size_t)KTOT * HH];
__device__ __nv_bfloat16 g_w1l[(size_t)KTOT * HH];
__device__ __nv_bfloat16 g_w2h[(size_t)KTOT * HH];
__device__ __nv_bfloat16 g_w2l[(size_t)KTOT * HH];
__device__ int g_cnt[3];

// ---------------------------------------------------------------------------
// helpers
// ---------------------------------------------------------------------------
__device__ __forceinline__ uint32_t smem_u32(const void* p) {
    uint32_t a;
    asm("{ .reg .u64 t; cvta.to.shared.u64 t, %1; cvt.u32.u64 %0, t; }" : "=r"(a) : "l"(p));
    return a;
}

#define CPA16(dst, src) \
    asm volatile("cp.async.cg.shared.global [%0], [%1], 16;" :: "r"(dst), "l"(src))
#define CPA_COMMIT() asm volatile("cp.async.commit_group;" ::: "memory")

#define LDSM4T(r0, r1, r2, r3, addr) \
    asm volatile("ldmatrix.sync.aligned.m8n8.x4.trans.shared.b16 {%0,%1,%2,%3}, [%4];" \
                 : "=r"(r0), "=r"(r1), "=r"(r2), "=r"(r3) : "r"(addr) : "memory")

#define MMA16816(d, a, b0, b1) \
    asm volatile("mma.sync.aligned.m16n8k16.row.col.f32.bf16.bf16.f32 " \
                 "{%0,%1,%2,%3}, {%4,%5,%6,%7}, {%8,%9}, {%0,%1,%2,%3};" \
                 : "+f"((d)[0]), "+f"((d)[1]), "+f"((d)[2]), "+f"((d)[3]) \
                 : "r"((a)[0]), "r"((a)[1]), "r"((a)[2]), "r"((a)[3]), \
                   "r"(b0), "r"(b1))

// ---------------------------------------------------------------------------
// split + transpose x: [B, D] fp32 -> xT hi/lo bf16 [2048][B]
// ---------------------------------------------------------------------------
__global__ void split_xT_kernel(const float* __restrict__ x,
                                __nv_bfloat16* __restrict__ xh,
                                __nv_bfloat16* __restrict__ xl)
{
    __shared__ float t[64][33];
    int k0 = blockIdx.x * 32;        // 64 tiles
    int m0 = blockIdx.y * 64;        // 256 tiles
    int tid = threadIdx.x;

    int k = tid >> 3;                // 0..31
    int mm = (tid & 7) * 8;          // 0..56

    int r = tid >> 2;                // 0..63
    int c = (tid & 3) * 8;           // 0,8,16,24
    const float* src = x + (size_t)(m0 + r) * DD + k0 + c;
    float4 v0 = *(const float4*)src;
    float4 v1 = *(const float4*)(src + 4);
    t[r][c + 0] = v0.x; t[r][c + 1] = v0.y; t[r][c + 2] = v0.z; t[r][c + 3] = v0.w;
    t[r][c + 4] = v1.x; t[r][c + 5] = v1.y; t[r][c + 6] = v1.z; t[r][c + 7] = v1.w;
    __syncthreads();

    __nv_bfloat16 h8[8], l8[8];
#pragma unroll
    for (int j = 0; j < 8; ++j) {
        float v = t[mm + j][k];
        __nv_bfloat16 h = __float2bfloat16(v);
        h8[j] = h;
        l8[j] = __float2bfloat16(v - __bfloat162float(h));
    }
    *(uint4*)(xh + (size_t)(k0 + k) * BB + m0 + mm) = *(uint4*)h8;
    *(uint4*)(xl + (size_t)(k0 + k) * BB + m0 + mm) = *(uint4*)l8;
}

// ---------------------------------------------------------------------------
// split W: [2048, 1024] fp32 -> hi/lo bf16 [2048][1024]
// ---------------------------------------------------------------------------
__global__ void split_w_kernel(const float* __restrict__ W,
                               __nv_bfloat16* __restrict__ wh,
                               __nv_bfloat16* __restrict__ wl)
{
    int idx = blockIdx.x * 256 + threadIdx.x;   // over 2048*1024
    float v = W[idx];
    __nv_bfloat16 h = __float2bfloat16(v);
    wh[idx] = h;
    wl[idx] = __float2bfloat16(v - __bfloat162float(h));
}

// ---------------------------------------------------------------------------
// HMMA split-bf16 GEMM (round-4/7 proven version): BK=32, 2-stage cp.async.
// CTA tile 128x128, 8 warps (2m x 4n). Optional relu (uniform flag).
// ---------------------------------------------------------------------------
#define STG_BYTES 32768
#define GEMM_SMEM (2 * STG_BYTES + 1024)

__device__ __forceinline__ void gemm_ld_stage(
    uint32_t db, int s, int c,
    const __nv_bfloat16* __restrict__ Ah, const __nv_bfloat16* __restrict__ Al,
    const __nv_bfloat16* __restrict__ Wh, const __nv_bfloat16* __restrict__ Wl,
    int m0, int n0, int tid)
{
    int k  = tid >> 3;                 // 0..31
    int mc = (tid & 7) * 2;            // chunk pair
    uint32_t base = db + s * STG_BYTES;
    uint32_t d0 = k * 256 + ((mc ^ (k & 7)) << 4);
    uint32_t d1 = k * 256 + (((mc + 1) ^ (k & 7)) << 4);
    size_t ka = (size_t)(c * 32 + k);
    const char* pah = (const char*)(Ah + ka * BB + m0 + mc * 8);
    const char* pal = (const char*)(Al + ka * BB + m0 + mc * 8);
    const char* pwh = (const char*)(Wh + ka * HH + n0 + mc * 8);
    const char* pwl = (const char*)(Wl + ka * HH + n0 + mc * 8);
    CPA16(base + d0,         pah);      CPA16(base + d1,         pah + 16);
    CPA16(base + 8192  + d0, pal);      CPA16(base + 8192  + d1, pal + 16);
    CPA16(base + 16384 + d0, pwh);      CPA16(base + 16384 + d1, pwh + 16);
    CPA16(base + 24576 + d0, pwl);      CPA16(base + 24576 + d1, pwl + 16);
    CPA_COMMIT();
}

__global__ __launch_bounds__(256, 1)
void gemm_mma(const __nv_bfloat16* __restrict__ Ah, const __nv_bfloat16* __restrict__ Al,
              const __nv_bfloat16* __restrict__ Wh, const __nv_bfloat16* __restrict__ Wl,
              const float* __restrict__ bias, float* __restrict__ C, int nch, int dorelu)
{
    extern __shared__ char smem[];
    uint32_t db = (smem_u32(smem) + 1023) & ~1023u;
    int tid = threadIdx.x, lane = tid & 31, wid = tid >> 5;
    int wm = wid >> 2, wn = wid & 3;
    int m0 = blockIdx.y * 128, n0 = blockIdx.x * 128;

    int q = lane >> 3, r = lane & 7;
    int kq = ((q >> 1) << 3) + r;       // 0..15
    int sw = kq & 7;
    uint32_t offA[4], offB[2];
#pragma unroll
    for (int mt = 0; mt < 4; ++mt) {
        int cc = wm * 8 + mt * 2 + (q & 1);
        offA[mt] = kq * 256 + ((cc ^ sw) << 4);
    }
#pragma unroll
    for (int bt = 0; bt < 2; ++bt) {
        int cc = wn * 4 + bt * 2 + (q & 1);
        offB[bt] = kq * 256 + ((cc ^ sw) << 4);
    }

    float acc[4][4][4] = {};

    gemm_ld_stage(db, 0, 0, Ah, Al, Wh, Wl, m0, n0, tid);

    for (int c = 0; c < nch; ++c) {
        if (c + 1 < nch) {
            gemm_ld_stage(db, (c + 1) & 1, c + 1, Ah, Al, Wh, Wl, m0, n0, tid);
            asm volatile("cp.async.wait_group 1;" ::: "memory");
        } else {
            asm volatile("cp.async.wait_group 0;" ::: "memory");
        }
        __syncthreads();

        uint32_t sbase = db + (c & 1) * STG_BYTES;
#pragma unroll
        for (int ks = 0; ks < 2; ++ks) {
            uint32_t sb = sbase + ks * 4096;
            uint32_t ah[4][4], al_[4][4], bh_[2][4], bl_[2][4];
#pragma unroll
            for (int mt = 0; mt < 4; ++mt) {
                LDSM4T(ah[mt][0],  ah[mt][1],  ah[mt][2],  ah[mt][3],  sb + offA[mt]);
                LDSM4T(al_[mt][0], al_[mt][1], al_[mt][2], al_[mt][3], sb + 8192 + offA[mt]);
            }
#pragma unroll
            for (int bt = 0; bt < 2; ++bt) {
                LDSM4T(bh_[bt][0], bh_[bt][1], bh_[bt][2], bh_[bt][3], sb + 16384 + offB[bt]);
                LDSM4T(bl_[bt][0], bl_[bt][1], bl_[bt][2], bl_[bt][3], sb + 24576 + offB[bt]);
            }
#pragma unroll
            for (int mt = 0; mt < 4; ++mt)
#pragma unroll
                for (int nt = 0; nt < 4; ++nt) {
                    int bt = nt >> 1, p = nt & 1;
                    MMA16816(acc[mt][nt], ah[mt], bh_[bt][p], bh_[bt][p + 2]);
                }
#pragma unroll
            for (int mt = 0; mt < 4; ++mt)
#pragma unroll
                for (int nt = 0; nt < 4; ++nt) {
                    int bt = nt >> 1, p = nt & 1;
                    MMA16816(acc[mt][nt], ah[mt], bl_[bt][p], bl_[bt][p + 2]);
                }
#pragma unroll
            for (int mt = 0; mt < 4; ++mt)
#pragma unroll
                for (int nt = 0; nt < 4; ++nt) {
                    int bt = nt >> 1, p = nt & 1;
                    MMA16816(acc[mt][nt], al_[mt], bh_[bt][p], bh_[bt][p + 2]);
                }
        }
        __syncthreads();
    }

    int g = lane >> 2, t2 = (lane & 3) * 2;
#pragma unroll
    for (int nt = 0; nt < 4; ++nt) {
        int col = n0 + wn * 32 + nt * 8 + t2;
        float2 bv = *(const float2*)(bias + col);
#pragma unroll
        for (int mt = 0; mt < 4; ++mt) {
            int row = m0 + wm * 64 + mt * 16 + g;
            float2 o0, o1;
            if (dorelu) {
                o0.x = fmaxf(acc[mt][nt][0] + bv.x, 0.f);
                o0.y = fmaxf(acc[mt][nt][1] + bv.y, 0.f);
                o1.x = fmaxf(acc[mt][nt][2] + bv.x, 0.f);
                o1.y = fmaxf(acc[mt][nt][3] + bv.y, 0.f);
            } else {
                o0.x = acc[mt][nt][0] + bv.x;
                o0.y = acc[mt][nt][1] + bv.y;
                o1.x = acc[mt][nt][2] + bv.x;
                o1.y = acc[mt][nt][3] + bv.y;
            }
            *(float2*)(C + (size_t)row * HH + col) = o0;
            *(float2*)(C + (size_t)(row + 8) * HH + col) = o1;
        }
    }
}

// ---------------------------------------------------------------------------
// Stats kernel: register-resident; moments + top-409 |x| sum via 2-pass radix
// (16 prefix bits + threshold correction). Fused k-predictor.
// ---------------------------------------------------------------------------
__global__ void stats_kernel(const float* __restrict__ x, float* __restrict__ stats,
                             const float* __restrict__ Wk1, const float* __restrict__ bk1,
                             const float* __restrict__ Wk2, const float* __restrict__ bk2)
{
    __shared__ float red[48];
    __shared__ float sres[8];
    __shared__ int hist[256];
    __shared__ int warptot[8];
    __shared__ unsigned s_pref;
    __shared__ int s_need;

    int row = blockIdx.x;
    int tid = threadIdx.x;
    int lane = tid & 31, w = tid >> 5;

    const float4* xr = (const float4*)(x + (size_t)row * DD);
    float4 a4 = xr[tid * 2], b4 = xr[tid * 2 + 1];
    float v[8] = {a4.x, a4.y, a4.z, a4.w, b4.x, b4.y, b4.z, b4.w};
    unsigned bb[8];
#pragma unroll
    for (int j = 0; j < 8; ++j) bb[j] = __float_as_uint(v[j]) & 0x7fffffffu;

    float sum = 0.f, sumsq = 0.f, suma = 0.f, zc = 0.f, maxa = 0.f;
#pragma unroll
    for (int j = 0; j < 8; ++j) {
        float vv = v[j];
        sum += vv; sumsq += vv * vv;
        float ab = fabsf(vv);
        suma += ab; maxa = fmaxf(maxa, ab);
        zc += (vv == 0.0f) ? 1.f : 0.f;
    }
#pragma unroll
    for (int o = 16; o; o >>= 1) {
        sum   += __shfl_down_sync(0xffffffffu, sum,   o);
        sumsq += __shfl_down_sync(0xffffffffu, sumsq, o);
        suma  += __shfl_down_sync(0xffffffffu, suma,  o);
        zc    += __shfl_down_sync(0xffffffffu, zc,    o);
        maxa   = fmaxf(maxa, __shfl_down_sync(0xffffffffu, maxa, o));
    }
    if (lane == 0) {
        red[w * 5 + 0] = sum;  red[w * 5 + 1] = sumsq; red[w * 5 + 2] = suma;
        red[w * 5 + 3] = zc;   red[w * 5 + 4] = maxa;
    }
    __syncthreads();
    if (tid < 5) {
        float r0 = red[tid];
        if (tid < 4) { for (int w2 = 1; w2 < 8; ++w2) r0 += red[w2 * 5 + tid]; }
        else         { for (int w2 = 1; w2 < 8; ++w2) r0 = fmaxf(r0, red[w2 * 5 + tid]); }
        sres[tid] = r0;
    }
    __syncthreads();
    sum = sres[0]; sumsq = sres[1]; suma = sres[2]; zc = sres[3]; maxa = sres[4];
    float mean = sum * (1.0f / 2048.0f);

    float s2 = 0.f, s3 = 0.f;
#pragma unroll
    for (int j = 0; j < 8; ++j) {
        float d = v[j] - mean;
        s2 += d * d;
        s3 += d * d * d;
    }
#pragma unroll
    for (int o = 16; o; o >>= 1) {
        s2 += __shfl_down_sync(0xffffffffu, s2, o);
        s3 += __shfl_down_sync(0xffffffffu, s3, o);
    }
    __syncthreads();
    if (lane == 0) { red[w * 2 + 0] = s2; red[w * 2 + 1] = s3; }
    __syncthreads();
    if (tid < 2) {
        float r0 = red[tid];
        for (int w2 = 1; w2 < 8; ++w2) r0 += red[w2 * 2 + tid];
        sres[5 + tid] = r0;
    }
    __syncthreads();
    s2 = sres[5]; s3 = sres[6];
    float var  = s2 * (1.0f / 2047.0f);
    float stdv = sqrtf(var + 1e-8f);
    float skew = (s3 * (1.0f / 2048.0f)) / (stdv * stdv * stdv);

    unsigned prefix = 0;
    int need = TOPC;
#pragma unroll
    for (int pass = 0; pass < 2; ++pass) {
        int shift = (pass == 0) ? 23 : 15;
        hist[tid] = 0;
        __syncthreads();
#pragma unroll
        for (int j = 0; j < 8; ++j) {
            bool match = (pass == 0) || ((bb[j] >> 23) == prefix);
            unsigned bin = (bb[j] >> shift) & 255;
            unsigned key = match ? bin : 0xffffffffu;
            unsigned grp = __match_any_sync(0xffffffffu, key);
            int leader = __ffs(grp) - 1;
            if (match && lane == leader)
                atomicAdd(&hist[bin], __popc(grp));
        }
        __syncthreads();
        int h = hist[tid];
        int suf = h;
#pragma unroll
        for (int o = 1; o < 32; o <<= 1) {
            int t = __shfl_down_sync(0xffffffffu, suf, o);
            if (lane + o < 32) suf += t;
        }
        if (lane == 0) warptot[w] = suf;
        __syncthreads();
        int tail = 0;
#pragma unroll
        for (int w2 = 0; w2 < 8; ++w2)
            if (w2 > w) tail += warptot[w2];
        int incl = suf + tail;
        int excl = incl - h;
        if (excl < need && need <= incl) {
            s_pref = (prefix << 8) | (unsigned)tid;
            s_need = need - excl;
        }
        __syncthreads();
        prefix = s_pref;
        need = s_need;
        __syncthreads();
    }

    unsigned tb = prefix << 15;
    float tsum = 0.f;
    int tcnt = 0;
#pragma unroll
    for (int j = 0; j < 8; ++j)
        if (bb[j] >= tb) { tsum += __uint_as_float(bb[j]); tcnt++; }
#pragma unroll
    for (int o = 16; o; o >>= 1) {
        tsum += __shfl_down_sync(0xffffffffu, tsum, o);
        tcnt += __shfl_down_sync(0xffffffffu, tcnt, o);
    }
    if (lane == 0) { red[w] = tsum; warptot[w] = tcnt; }
    __syncthreads();
    if (tid == 0) {
        float tt = 0.f; int nc = 0;
        for (int w2 = 0; w2 < 8; ++w2) { tt += red[w2]; nc += warptot[w2]; }
        float tmid = __uint_as_float(tb + (1u << 14));
        tt -= (float)(nc - TOPC) * tmid;
        float st[6];
        st[0] = zc * (1.0f / 2048.0f);
        st[1] = var;
        st[2] = maxa;
        st[3] = sqrtf(sumsq);
        st[4] = skew;
        st[5] = tt / (suma + 1e-8f);
        float* o = stats + (size_t)row * 6;
#pragma unroll
        for (int i = 0; i < 6; ++i) o[i] = st[i];

        float kp = bk2[0];
#pragma unroll
        for (int hh = 0; hh < 16; ++hh) {
            float z = bk1[hh];
#pragma unroll
            for (int i = 0; i < 6; ++i) z += st[i] * Wk1[i * 16 + hh];
            kp += fmaxf(z, 0.f) * Wk2[hh];
        }
        float kv = 1.0f / (1.0f + expf(-kp));
        float val = 1.0f + 3.0f * kv;
        if (val < 2.0f) atomicAdd(&g_cnt[0], 1);
        if (val < 3.0f) atomicAdd(&g_cnt[1], 1);
        if (val < 4.0f) atomicAdd(&g_cnt[2], 1);
    }
}

// ---------------------------------------------------------------------------
// sims kernel: sims = x @ patterns^T
// ---------------------------------------------------------------------------
__global__ void sims_kernel(const float* __restrict__ x, const float* __restrict__ pat,
                            float* __restrict__ sims)
{
    __shared__ float xs[64][68];
    __shared__ float ws[64][16];
    int tid = threadIdx.x;
    int row0 = blockIdx.x * 64;
    int e = tid & 15;
    int r0 = (tid >> 4) * 4;
    float acc[4] = {};

    for (int kc = 0; kc < DD; kc += 64) {
#pragma unroll
        for (int it = 0; it < 4; ++it) {
            int idx = tid + it * 256;
            int r = idx >> 4, c4 = idx & 15;
            *(float4*)&xs[r][c4 * 4] =
                *(const float4*)(x + (size_t)(row0 + r) * DD + kc + c4 * 4);
        }
        {
            int pe = tid & 15, k4 = tid >> 4;
            float4 v = *(const float4*)(pat + (size_t)pe * DD + kc + k4 * 4);
            ws[k4 * 4 + 0][pe] = v.x; ws[k4 * 4 + 1][pe] = v.y;
            ws[k4 * 4 + 2][pe] = v.z; ws[k4 * 4 + 3][pe] = v.w;
        }
        __syncthreads();
#pragma unroll 4
        for (int k = 0; k < 64; ++k) {
            float wv = ws[k][e];
            acc[0] += xs[r0 + 0][k] * wv;
            acc[1] += xs[r0 + 1][k] * wv;
            acc[2] += xs[r0 + 2][k] * wv;
            acc[3] += xs[r0 + 3][k] * wv;
        }
        __syncthreads();
    }
#pragma unroll
    for (int j = 0; j < 4; ++j)
        sims[(size_t)(row0 + r0 + j) * EE + e] = acc[j];
}

// ---------------------------------------------------------------------------
// spec2 kernel (fp32 only): spec = sigmoid(sims + h1@Ws2 + bs2)
// ---------------------------------------------------------------------------
__global__ void spec2_kernel(const float* __restrict__ sims,
                             const float* __restrict__ h1, const float* __restrict__ Ws2,
                             const float* __restrict__ bs2, float* __restrict__ spec)
{
    __shared__ float xs[64][68];
    __shared__ float ws[64][16];
    int tid = threadIdx.x;
    int row0 = blockIdx.x * 64;
    int e = tid & 15;
    int r0 = (tid >> 4) * 4;
    float acc[4];
#pragma unroll
    for (int j = 0; j < 4; ++j)
        acc[j] = sims[(size_t)(row0 + r0 + j) * EE + e];

    for (int kc = 0; kc < HH; kc += 64) {
#pragma unroll
        for (int it = 0; it < 4; ++it) {
            int idx = tid + it * 256;
            int r = idx >> 4, c4 = idx & 15;
            *(float4*)&xs[r][c4 * 4] =
                *(const float4*)(h1 + (size_t)(row0 + r) * HH + kc + c4 * 4);
        }
        {
            int k = tid >> 2, e4 = tid & 3;
            *(float4*)&ws[k][e4 * 4] =
                *(const float4*)(Ws2 + (size_t)(kc + k) * EE + e4 * 4);
        }
        __syncthreads();
#pragma unroll 4
        for (int k = 0; k < 64; ++k) {
            float wv = ws[k][e];
            acc[0] += xs[r0 + 0][k] * wv;
            acc[1] += xs[r0 + 1][k] * wv;
            acc[2] += xs[r0 + 2][k] * wv;
            acc[3] += xs[r0 + 3][k] * wv;
        }
        __syncthreads();
    }
    float b = bs2[e];
#pragma unroll
    for (int j = 0; j < 4; ++j) {
        float vv = acc[j] + b;
        spec[(size_t)(row0 + r0 + j) * EE + e] = 1.0f / (1.0f + expf(-vv));
    }
}

// ---------------------------------------------------------------------------
// probs kernel with fused rank-16 update:
//   h2 = relu(h2raw + spec @ Wr1tail); probs = softmax(h2 @ Wr2 + br2)
// h2raw already includes br1 (added by GEMM2 epilogue).
// ---------------------------------------------------------------------------
__global__ void probs_r16_kernel(const float* __restrict__ h2raw,
                                 const float* __restrict__ spec,
                                 const float* __restrict__ wr1t,  // [16][1024] fp32
                                 const float* __restrict__ Wr2,
                                 const float* __restrict__ br2, float* __restrict__ probs)
{
    __shared__ float xs[64][68];
    __shared__ float ws[64][16];
    __shared__ float wt[16][68];
    __shared__ float sp[64][17];
    __shared__ float lg[64][17];
    int tid = threadIdx.x;
    int row0 = blockIdx.x * 64;
    int e = tid & 15;
    int r0 = (tid >> 4) * 4;
    float acc[4] = {};

    // load spec block (64 x 16) once
    {
        int r = tid >> 2, c4 = (tid & 3) * 4;
        float4 v = *(const float4*)(spec + (size_t)(row0 + r) * EE + c4);
        sp[r][c4 + 0] = v.x; sp[r][c4 + 1] = v.y;
        sp[r][c4 + 2] = v.z; sp[r][c4 + 3] = v.w;
    }

    for (int kc = 0; kc < HH; kc += 64) {
        // load Wr1tail slice (16 x 64) and Wr2 slice (64 x 16)
        {
            int t = tid >> 4, c4 = (tid & 15) * 4;
            float4 v = *(const float4*)(wr1t + (size_t)t * HH + kc + c4);
            wt[t][c4 + 0] = v.x; wt[t][c4 + 1] = v.y;
            wt[t][c4 + 2] = v.z; wt[t][c4 + 3] = v.w;
        }
        {
            int k = tid >> 2, e4 = tid & 3;
            *(float4*)&ws[k][e4 * 4] =
                *(const float4*)(Wr2 + (size_t)(kc + k) * EE + e4 * 4);
        }
        __syncthreads();
        // compute xs = relu(h2raw + sp·wt)
#pragma unroll
        for (int it = 0; it < 4; ++it) {
            int idx = tid + it * 256;
            int r = idx >> 4, c4 = (idx & 15) * 4;
            float4 v = *(const float4*)(h2raw + (size_t)(row0 + r) * HH + kc + c4);
            float vv[4] = {v.x, v.y, v.z, v.w};
#pragma unroll
            for (int j = 0; j < 4; ++j) {
                float s = vv[j];
#pragma unroll
                for (int t = 0; t < 16; ++t)
                    s += sp[r][t] * wt[t][c4 + j];
                xs[r][c4 + j] = fmaxf(s, 0.0f);
            }
        }
        __syncthreads();
#pragma unroll 4
        for (int k = 0; k < 64; ++k) {
            float wv = ws[k][e];
            acc[0] += xs[r0 + 0][k] * wv;
            acc[1] += xs[r0 + 1][k] * wv;
            acc[2] += xs[r0 + 2][k] * wv;
            acc[3] += xs[r0 + 3][k] * wv;
        }
        __syncthreads();
    }
    float b = br2[e];
#pragma unroll
    for (int j = 0; j < 4; ++j) lg[r0 + j][e] = acc[j] + b;
    __syncthreads();

    if (tid < 64) {
        int r = tid;
        float m = -3.4e38f;
#pragma unroll
        for (int k = 0; k < 16; ++k) m = fmaxf(m, lg[r][k]);
        float pv[16]; float s = 0.f;
#pragma unroll
        for (int k = 0; k < 16; ++k) { pv[k] = expf(lg[r][k] - m); s += pv[k]; }
        float inv = 1.0f / s;
        float* o = probs + (size_t)(row0 + r) * EE;
#pragma unroll
        for (int k = 0; k < 16; ++k) o[k] = pv[k] * inv;
    }
}

// ---------------------------------------------------------------------------
// top-k + gates (k derived per-thread from g_cnt counts; median = 8192nd)
// ---------------------------------------------------------------------------
__global__ void topk_kernel(const float* __restrict__ probs,
                            float* __restrict__ gates, float* __restrict__ idxo)
{
    int row = blockIdx.x * 256 + threadIdx.x;
    int c0 = g_cnt[0], c1 = g_cnt[1], c2 = g_cnt[2];
    int k = (c0 >= 8192) ? 1 : (c1 >= 8192) ? 2 : (c2 >= 8192) ? 3 : 4;

    float p[16];
    const float4* pr = (const float4*)(probs + (size_t)row * EE);
    ((float4*)p)[0] = pr[0]; ((float4*)p)[1] = pr[1];
    ((float4*)p)[2] = pr[2]; ((float4*)p)[3] = pr[3];

    unsigned used = 0;
    float tv[4]; int ti[4];
#pragma unroll
    for (int s = 0; s < 4; ++s) {
        float bv = -1.0f; int bi = 0;
#pragma unroll
        for (int e = 0; e < 16; ++e) {
            bool ok = (((used >> e) & 1u) == 0u) && (p[e] > bv);
            if (ok) { bv = p[e]; bi = e; }
        }
        used |= (1u << bi);
        tv[s] = bv; ti[s] = bi;
    }
    float g[4]; float ssum = 0.f;
#pragma unroll
    for (int j = 0; j < 4; ++j) {
        g[j] = (j < k) ? expf(tv[j] - tv[0]) : 0.0f;
        ssum += g[j];
    }
    float inv = 1.0f / ssum;
#pragma unroll
    for (int j = 0; j < 4; ++j) {
        gates[(size_t)row * 4 + j] = g[j] * inv;
        idxo[(size_t)row * 4 + j] = (float)ti[j];
    }
}

// ---------------------------------------------------------------------------
__global__ void init_kernel() { g_cnt[0] = 0; g_cnt[1] = 0; g_cnt[2] = 0; }

// ---------------------------------------------------------------------------
extern "C" void kernel_launch(void* const* d_in, const int* in_sizes, int n_in,
                              void* d_out, int out_size)
{
    const float* x    = (const float*)d_in[0];
    const float* pat  = (const float*)d_in[1];
    const float* Ws1  = (const float*)d_in[2];
    const float* bs1  = (const float*)d_in[3];
    const float* Ws2  = (const float*)d_in[4];
    const float* bs2  = (const float*)d_in[5];
    const float* Wr1  = (const float*)d_in[6];
    const float* br1  = (const float*)d_in[7];
    const float* Wr2  = (const float*)d_in[8];
    const float* br2  = (const float*)d_in[9];
    const float* Wk1  = (const float*)d_in[10];
    const float* bk1  = (const float*)d_in[11];
    const float* Wk2  = (const float*)d_in[12];
    const float* bk2  = (const float*)d_in[13];

    float* out = (float*)d_out;
    float* o_gates = out;                      // 16384*4
    float* o_idx   = out + 65536;              // 16384*4
    float* o_probs = out + 131072;             // 16384*16
    float* o_stats = out + 393216;             // 16384*6

    void* p;
    cudaGetSymbolAddress(&p, g_h1);   float* h1 = (float*)p;
    cudaGetSymbolAddress(&p, g_h2);   float* h2raw = (float*)p;
    cudaGetSymbolAddress(&p, g_spec); float* spec = (float*)p;
    cudaGetSymbolAddress(&p, g_sims); float* sims = (float*)p;
    cudaGetSymbolAddress(&p, g_xth);  __nv_bfloat16* xth = (__nv_bfloat16*)p;
    cudaGetSymbolAddress(&p, g_xtl);  __nv_bfloat16* xtl = (__nv_bfloat16*)p;
    cudaGetSymbolAddress(&p, g_w1h);  __nv_bfloat16* w1h = (__nv_bfloat16*)p;
    cudaGetSymbolAddress(&p, g_w1l);  __nv_bfloat16* w1l = (__nv_bfloat16*)p;
    cudaGetSymbolAddress(&p, g_w2h);  __nv_bfloat16* w2h = (__nv_bfloat16*)p;
    cudaGetSymbolAddress(&p, g_w2l);  __nv_bfloat16* w2l = (__nv_bfloat16*)p;

    cudaFuncSetAttribute(gemm_mma, cudaFuncAttributeMaxDynamicSharedMemorySize, GEMM_SMEM);

    // streams + events (created once; identical topology per call)
    // s1: low-prio side work; s2: low-prio GEMM2; s3: high-prio epilogue chain
    static cudaStream_t s1 = 0, s2 = 0, s3 = 0;
    static cudaEvent_t evF = 0, evXT = 0, evW1 = 0, evW2 = 0, evA = 0, evB = 0,
                       evG2 = 0, evOut = 0;
    if (evOut == 0) {
        int lo, hi;
        cudaDeviceGetStreamPriorityRange(&lo, &hi);
        cudaStreamCreateWithPriority(&s1, cudaStreamNonBlocking, lo);
        cudaStreamCreateWithPriority(&s2, cudaStreamNonBlocking, lo);
        cudaStreamCreateWithPriority(&s3, cudaStreamNonBlocking, hi);
        cudaEventCreateWithFlags(&evF,  cudaEventDisableTiming);
        cudaEventCreateWithFlags(&evXT, cudaEventDisableTiming);
        cudaEventCreateWithFlags(&evW1, cudaEventDisableTiming);
        cudaEventCreateWithFlags(&evW2, cudaEventDisableTiming);
        cudaEventCreateWithFlags(&evA,  cudaEventDisableTiming);
        cudaEventCreateWithFlags(&evB,  cudaEventDisableTiming);
        cudaEventCreateWithFlags(&evG2, cudaEventDisableTiming);
        cudaEventCreateWithFlags(&evOut, cudaEventDisableTiming);
    }

    // fork everything from the main (default) stream
    cudaEventRecord(evF, 0);
    cudaStreamWaitEvent(s1, evF, 0);
    cudaStreamWaitEvent(s2, evF, 0);
    cudaStreamWaitEvent(s3, evF, 0);

    // ---- s1 (low): side work ----
    init_kernel<<<1, 1, 0, s1>>>();
    split_w_kernel<<<(KTOT * HH) / 256, 256, 0, s1>>>(Wr1, w2h, w2l);   // Wr1 main [0,2048)
    cudaEventRecord(evW2, s1);
    sims_kernel<<<BB / 64, 256, 0, s1>>>(x, pat, sims);
    cudaEventRecord(evA, s1);                    // sims ready
    stats_kernel<<<BB, 256, 0, s1>>>(x, o_stats, Wk1, bk1, Wk2, bk2);
    cudaEventRecord(evB, s1);                    // g_cnt ready

    // ---- default stream: input prep ----
    {
        dim3 tg(KTOT / 32, BB / 64);
        split_xT_kernel<<<tg, 256>>>(x, xth, xtl);
    }
    cudaEventRecord(evXT, 0);
    split_w_kernel<<<(KTOT * HH) / 256, 256>>>(Ws1, w1h, w1l);
    cudaEventRecord(evW1, 0);

    dim3 gg(HH / 128, BB / 128);

    // ---- s3 (high): GEMM1 -> spec2 -> probs -> topk ----
    cudaStreamWaitEvent(s3, evW1, 0);            // implies evXT too (same stream order)
    gemm_mma<<<gg, 256, GEMM_SMEM, s3>>>(xth, xtl, w1h, w1l, bs1, h1, 64, 1);

    // ---- s2 (low): GEMM2 main (K=2048, no spec dependency, no relu) ----
    cudaStreamWaitEvent(s2, evXT, 0);
    cudaStreamWaitEvent(s2, evW2, 0);
    gemm_mma<<<gg, 256, GEMM_SMEM, s2>>>(xth, xtl, w2h, w2l, br1, h2raw, 64, 0);
    cudaEventRecord(evG2, s2);

    // ---- s3 continues: spec2 overlaps GEMM2 remainder ----
    cudaStreamWaitEvent(s3, evA, 0);             // need sims
    spec2_kernel<<<BB / 64, 256, 0, s3>>>(sims, h1, Ws2, bs2, spec);

    cudaStreamWaitEvent(s3, evG2, 0);            // need h2raw
    cudaStreamWaitEvent(s3, evB, 0);             // need g_cnt (for topk below)
    probs_r16_kernel<<<BB / 64, 256, 0, s3>>>(h2raw, spec,
                                              Wr1 + (size_t)DD * HH,  // tail rows [2048,2064)
                                              Wr2, br2, o_probs);
    topk_kernel<<<BB / 256, 256, 0, s3>>>(o_probs, o_gates, o_idx);
    cudaEventRecord(evOut, s3);

    // join everything back into the main stream
    cudaStreamWaitEvent(0, evOut, 0);

    (void)in_sizes; (void)n_in; (void)out_size;
}